// round 9
// baseline (speedup 1.0000x reference)
#include <cuda_runtime.h>
#include <cstdint>

// Problem dims (fixed by dataset)
constexpr int Bb = 4;      // batch
constexpr int Nq = 4096;   // H*W
constexpr int C  = 256;    // channels
constexpr int CK = 32;     // key/query channels

// Scratch in __device__ globals (allocation-free rule)
__device__ float g_f [(size_t)Bb * Nq * CK];             // keys   (tf32 hi)
__device__ float g_fl[(size_t)Bb * Nq * CK];             // keys   (lo residual)
__device__ float g_g [(size_t)Bb * Nq * CK];             // queries(tf32 hi)
__device__ float g_gl[(size_t)Bb * Nq * CK];             // queries(lo residual)
__device__ float g_hT[(size_t)Bb * C * Nq];              // values, transposed, tf32-rounded
__device__ float g_s [(size_t)Bb * Nq * Nq];             // raw scores (256 MB)
__device__ float g_WT  [320 * 256];                      // [Wf|Wg|Wh]^T, tf32 hi
__device__ float g_WTlo[64 * 256];                       // lo residual for f,g cols

__device__ __forceinline__ uint32_t smem_u32(const void* p) {
    return (uint32_t)__cvta_generic_to_shared(p);
}
__device__ __forceinline__ void cp16(uint32_t s, const void* g) {
    asm volatile("cp.async.cg.shared.global [%0], [%1], 16;" :: "r"(s), "l"(g));
}
__device__ __forceinline__ void cp_commit() {
    asm volatile("cp.async.commit_group;" ::: "memory");
}
__device__ __forceinline__ uint32_t f2tf32(float f) {
    uint32_t u;
    asm("cvt.rna.tf32.f32 %0, %1;" : "=r"(u) : "f"(f));
    return u;
}
__device__ __forceinline__ void mma_tf32(float* d, const uint32_t* a, const uint32_t* bfr) {
    asm volatile(
        "mma.sync.aligned.m16n8k8.row.col.f32.tf32.tf32.f32 "
        "{%0,%1,%2,%3}, {%4,%5,%6,%7}, {%8,%9}, {%0,%1,%2,%3};"
        : "+f"(d[0]), "+f"(d[1]), "+f"(d[2]), "+f"(d[3])
        : "r"(a[0]), "r"(a[1]), "r"(a[2]), "r"(a[3]), "r"(bfr[0]), "r"(bfr[1]));
}
__device__ __forceinline__ void ldsm4(uint32_t* r, uint32_t a) {
    asm volatile("ldmatrix.sync.aligned.m8n8.x4.shared.b16 {%0,%1,%2,%3}, [%4];"
        : "=r"(r[0]), "=r"(r[1]), "=r"(r[2]), "=r"(r[3]) : "r"(a));
}
__device__ __forceinline__ void ldsm2(uint32_t* r, uint32_t a) {
    asm volatile("ldmatrix.sync.aligned.m8n8.x2.shared.b16 {%0,%1}, [%2];"
        : "=r"(r[0]), "=r"(r[1]) : "r"(a));
}

// ===========================================================================
// Kernel 0: W pre-transpose + tf32 hi/lo pre-split (one-shot, tiny)
// ===========================================================================
__global__ void wtrans_kernel(const float* __restrict__ Wf,
                              const float* __restrict__ Wg,
                              const float* __restrict__ Wh) {
    int idx = blockIdx.x * 256 + threadIdx.x;       // 320*256 total
    int n = idx >> 8, k = idx & 255;
    float w;
    if (n < 32)       w = Wf[k * CK + n];
    else if (n < 64)  w = Wg[k * CK + (n - 32)];
    else              w = Wh[k * C + (n - 64)];
    uint32_t hi = f2tf32(w);
    g_WT[n * 256 + k] = __uint_as_float(hi);
    if (n < 64)
        g_WTlo[n * 256 + k] = __uint_as_float(f2tf32(w - __uint_as_float(hi)));
}

// ===========================================================================
// Kernel 1: fused projections via ldmatrix + tensor cores. (unchanged R8)
// ===========================================================================
constexpr int PJ_SMEM = (64 * 36 + 320 * 36 + 64 * 36) * 4;   // 64,512 B

__global__ __launch_bounds__(256, 2)
void proj_kernel(const float* __restrict__ x,
                 const float* __restrict__ bfv, const float* __restrict__ bgv,
                 const float* __restrict__ bhv) {
    extern __shared__ float sm[];
    float* Xs  = sm;                   // [64][36]
    float* Whs = sm + 64 * 36;         // [320][36]
    float* Wls = sm + 64 * 36 + 320 * 36;  // [64][36]

    const int t = threadIdx.x;
    const int lane = t & 31, wid = t >> 5;
    const int wm = wid >> 2, wn = wid & 3;
    const int rowbase = blockIdx.x * 64;

    const int arow = (lane & 7) + ((lane >> 3) & 1) * 8;
    const int acol = (lane >> 4) * 4;
    const int brow2 = lane & 7;
    const int bcol2 = ((lane >> 3) & 1) * 4;

    const uint32_t XsU = smem_u32(Xs), WhU = smem_u32(Whs), WlU = smem_u32(Wls);

    float acc[2][10][4] = {};

    for (int ch = 0; ch < 8; ch++) {
        const int k0 = ch * 32;
        __syncthreads();
        #pragma unroll
        for (int i = 0; i < 2; i++) {
            int idx = t + i * 256;
            int r = idx >> 3, c4 = (idx & 7) * 4;
            cp16(XsU + (r * 36 + c4) * 4, x + (size_t)(rowbase + r) * C + k0 + c4);
        }
        #pragma unroll
        for (int i = 0; i < 10; i++) {
            int idx = t + i * 256;
            int r = idx >> 3, c4 = (idx & 7) * 4;
            cp16(WhU + (r * 36 + c4) * 4, g_WT + r * 256 + k0 + c4);
        }
        #pragma unroll
        for (int i = 0; i < 2; i++) {
            int idx = t + i * 256;
            int r = idx >> 3, c4 = (idx & 7) * 4;
            cp16(WlU + (r * 36 + c4) * 4, g_WTlo + r * 256 + k0 + c4);
        }
        cp_commit();
        asm volatile("cp.async.wait_group 0;" ::: "memory");
        __syncthreads();

        #pragma unroll
        for (int ks = 0; ks < 4; ks++) {
            uint32_t xr[2][4], ah[2][4], al[2][4];
            #pragma unroll
            for (int mt = 0; mt < 2; mt++) {
                ldsm4(xr[mt], XsU + ((wm * 32 + mt * 16 + arow) * 36 + ks * 8 + acol) * 4);
                #pragma unroll
                for (int e = 0; e < 4; e++) {
                    float v = __uint_as_float(xr[mt][e]);
                    ah[mt][e] = f2tf32(v);
                    al[mt][e] = f2tf32(v - __uint_as_float(ah[mt][e]));
                }
            }
            #pragma unroll
            for (int nt = 0; nt < 10; nt++) {
                const int c0 = nt * 32 + wn * 8;
                uint32_t bh[2];
                ldsm2(bh, WhU + ((c0 + brow2) * 36 + ks * 8 + bcol2) * 4);
                if (nt < 2) {
                    uint32_t bl[2];
                    ldsm2(bl, WlU + ((c0 + brow2) * 36 + ks * 8 + bcol2) * 4);
                    #pragma unroll
                    for (int mt = 0; mt < 2; mt++) {
                        mma_tf32(acc[mt][nt], ah[mt], bh);
                        mma_tf32(acc[mt][nt], ah[mt], bl);
                        mma_tf32(acc[mt][nt], al[mt], bh);
                    }
                } else {
                    #pragma unroll
                    for (int mt = 0; mt < 2; mt++)
                        mma_tf32(acc[mt][nt], ah[mt], bh);
                }
            }
        }
    }

    #pragma unroll
    for (int nt = 0; nt < 10; nt++) {
        const int c0 = nt * 32 + wn * 8 + 2 * (lane & 3);
        #pragma unroll
        for (int mt = 0; mt < 2; mt++) {
            const int r0 = rowbase + wm * 32 + mt * 16 + (lane >> 2);
            #pragma unroll
            for (int h = 0; h < 2; h++) {
                const int r = r0 + h * 8;
                const float d0 = acc[mt][nt][h * 2 + 0];
                const float d1 = acc[mt][nt][h * 2 + 1];
                if (nt == 0) {
                    float v0 = d0 + bfv[c0], v1 = d1 + bfv[c0 + 1];
                    uint32_t h0 = f2tf32(v0), h1 = f2tf32(v1);
                    float2 oh; oh.x = __uint_as_float(h0); oh.y = __uint_as_float(h1);
                    float2 ol;
                    ol.x = __uint_as_float(f2tf32(v0 - oh.x));
                    ol.y = __uint_as_float(f2tf32(v1 - oh.y));
                    *(float2*)(g_f  + (size_t)r * CK + c0) = oh;
                    *(float2*)(g_fl + (size_t)r * CK + c0) = ol;
                } else if (nt == 1) {
                    int c = c0 - 32;
                    float v0 = d0 + bgv[c], v1 = d1 + bgv[c + 1];
                    uint32_t h0 = f2tf32(v0), h1 = f2tf32(v1);
                    float2 oh; oh.x = __uint_as_float(h0); oh.y = __uint_as_float(h1);
                    float2 ol;
                    ol.x = __uint_as_float(f2tf32(v0 - oh.x));
                    ol.y = __uint_as_float(f2tf32(v1 - oh.y));
                    *(float2*)(g_g  + (size_t)r * CK + c) = oh;
                    *(float2*)(g_gl + (size_t)r * CK + c) = ol;
                } else {
                    int c = c0 - 64;
                    int bb = r >> 12, n = r & 4095;
                    g_hT[((size_t)bb * C + c) * Nq + n] =
                        __uint_as_float(f2tf32(d0 + bhv[c]));
                    g_hT[((size_t)bb * C + c + 1) * Nq + n] =
                        __uint_as_float(f2tf32(d1 + bhv[c + 1]));
                }
            }
        }
    }
}

// ===========================================================================
// Kernel 2: scores, pre-split hi/lo inputs -> pure LDSM + HMMA loop. (R8)
// ===========================================================================
constexpr int SC_SMEM = 4 * 128 * 36 * 4;   // 73,728 B

__global__ __launch_bounds__(256)
void score_kernel() {
    extern __shared__ float sm[];
    float* Gh = sm;
    float* Gl = sm + 4608;
    float* Fh = sm + 9216;
    float* Fl = sm + 13824;

    const int t = threadIdx.x;
    const int lane = t & 31, wid = t >> 5;
    const int wm = wid >> 2, wn = wid & 3;
    const int mbase = blockIdx.y * 128, nbase = blockIdx.x * 128;
    const size_t zoff = (size_t)blockIdx.z * Nq * CK;

    #pragma unroll
    for (int i = 0; i < 4; i++) {
        int idx = t + i * 256;
        int r = idx >> 3, c4 = (idx & 7) * 4;
        *(float4*)(Gh + r * 36 + c4) = *(const float4*)(g_g  + zoff + (size_t)(mbase + r) * CK + c4);
        *(float4*)(Gl + r * 36 + c4) = *(const float4*)(g_gl + zoff + (size_t)(mbase + r) * CK + c4);
        *(float4*)(Fh + r * 36 + c4) = *(const float4*)(g_f  + zoff + (size_t)(nbase + r) * CK + c4);
        *(float4*)(Fl + r * 36 + c4) = *(const float4*)(g_fl + zoff + (size_t)(nbase + r) * CK + c4);
    }
    __syncthreads();

    const int arow = (lane & 7) + ((lane >> 3) & 1) * 8;
    const int acol = (lane >> 4) * 4;
    const int brow = (lane >> 4) * 8 + (lane & 7);
    const int bcol = ((lane >> 3) & 1) * 4;
    const uint32_t GhU = smem_u32(Gh), GlU = smem_u32(Gl);
    const uint32_t FhU = smem_u32(Fh), FlU = smem_u32(Fl);

    float acc[4][4][4] = {};
    #pragma unroll
    for (int ks = 0; ks < 4; ks++) {
        uint32_t ah[4][4], al[4][4];
        #pragma unroll
        for (int mt = 0; mt < 4; mt++) {
            uint32_t off = ((wm * 64 + mt * 16 + arow) * 36 + ks * 8 + acol) * 4;
            ldsm4(ah[mt], GhU + off);
            ldsm4(al[mt], GlU + off);
        }
        #pragma unroll
        for (int j = 0; j < 2; j++) {
            uint32_t bh[4], bl[4];
            uint32_t off = ((wn * 32 + j * 16 + brow) * 36 + ks * 8 + bcol) * 4;
            ldsm4(bh, FhU + off);
            ldsm4(bl, FlU + off);
            #pragma unroll
            for (int sub = 0; sub < 2; sub++) {
                #pragma unroll
                for (int mt = 0; mt < 4; mt++) {
                    mma_tf32(acc[mt][2 * j + sub], ah[mt], bh + sub * 2);
                    mma_tf32(acc[mt][2 * j + sub], ah[mt], bl + sub * 2);
                    mma_tf32(acc[mt][2 * j + sub], al[mt], bh + sub * 2);
                }
            }
        }
    }

    float* sout = g_s + (size_t)blockIdx.z * Nq * Nq;
    #pragma unroll
    for (int mt = 0; mt < 4; mt++) {
        int r0 = mbase + wm * 64 + mt * 16 + (lane >> 2);
        #pragma unroll
        for (int nt = 0; nt < 4; nt++) {
            int col = nbase + wn * 32 + nt * 8 + 2 * (lane & 3);
            float2 o0; o0.x = acc[mt][nt][0]; o0.y = acc[mt][nt][1];
            *(float2*)(sout + (size_t)r0 * Nq + col) = o0;
            float2 o1; o1.x = acc[mt][nt][2]; o1.y = acc[mt][nt][3];
            *(float2*)(sout + (size_t)(r0 + 8) * Nq + col) = o1;
        }
    }
}

// ===========================================================================
// Kernel 3: fused exp-softmax + PV + residual.
//   CTA tile 64(q) x 256(C), 256 threads, 8 warps (2m x 4n), warp 32x64.
//   2 CTAs/SM (grid 256) -> barrier/wait latency hidden by sibling CTA.
//   A: 3-stage exp->STS pipeline; B: 2-stage cp.async double buffer.
// ===========================================================================
constexpr int PV_AROW = 36;
constexpr int PV_AST  = 64 * PV_AROW;              // 2304 floats
constexpr int PV_BST  = 256 * PV_AROW;             // 9216 floats
constexpr int PV_SMEM = (3 * PV_AST + 2 * PV_BST + 64) * 4;   // 101,632 B
constexpr int NCH = Nq / 32;                       // 128

__global__ __launch_bounds__(256, 2)
void pv_kernel(const float* __restrict__ gamma_p,
               const float* __restrict__ x, float* __restrict__ y) {
    extern __shared__ float sm[];
    float* Abuf = sm;
    float* Bbuf = sm + 3 * PV_AST;
    float* zsm  = sm + 3 * PV_AST + 2 * PV_BST;

    const int t = threadIdx.x;
    const int lane = t & 31, wid = t >> 5;
    const int wm = wid >> 2, wn = wid & 3;         // 2(M) x 4(N)
    const int qbase = blockIdx.x * 64;
    const int b = blockIdx.y;
    const float* Pm  = g_s  + (size_t)b * Nq * Nq;
    const float* hTb = g_hT + (size_t)b * C * Nq;

    if (t < 64) zsm[t] = 0.f;

    const int tr  = t >> 3;          // 0..31
    const int tc4 = (t & 7) * 4;

    const int arow = (lane & 7) + ((lane >> 3) & 1) * 8;
    const int acol = (lane >> 4) * 4;
    const int brow = (lane >> 4) * 8 + (lane & 7);
    const int bcol = ((lane >> 3) & 1) * 4;

    float4 va[2], vb[2];
    float zp[2] = {0.f, 0.f};

    auto ldgA = [&](int chunk, float4* v) {
        const float* base = Pm + (size_t)(qbase + tr) * Nq + chunk * 32 + tc4;
        v[0] = *(const float4*)(base);
        v[1] = *(const float4*)(base + (size_t)32 * Nq);
    };
    auto expSts = [&](int chunk, const float4* v) {
        float* Ad = Abuf + (chunk % 3) * PV_AST;
        #pragma unroll
        for (int i = 0; i < 2; i++) {
            float4 p;
            p.x = __uint_as_float(f2tf32(__expf(v[i].x)));
            p.y = __uint_as_float(f2tf32(__expf(v[i].y)));
            p.z = __uint_as_float(f2tf32(__expf(v[i].z)));
            p.w = __uint_as_float(f2tf32(__expf(v[i].w)));
            zp[i] += (p.x + p.y) + (p.z + p.w);
            *(float4*)(Ad + (tr + 32 * i) * PV_AROW + tc4) = p;
        }
    };
    auto cpB = [&](int chunk) {
        float* Bd = Bbuf + (chunk & 1) * PV_BST;
        #pragma unroll
        for (int i = 0; i < 8; i++) {
            int idx = t + i * 256;
            int r = idx >> 3, c4 = (idx & 7) * 4;
            cp16(smem_u32(Bd + r * PV_AROW + c4),
                 hTb + (size_t)r * Nq + chunk * 32 + c4);
        }
        cp_commit();
    };

    // prologue: B stages 0,1; A stages 0,1; va = raw chunk 2
    cpB(0); cpB(1);
    ldgA(0, va); expSts(0, va);
    ldgA(1, va); expSts(1, va);
    ldgA(2, va);

    float acc[2][8][4] = {};   // warp tile 32(M) x 64(N)

    for (int c = 0; c < NCH; c++) {
        if (c + 2 < NCH) expSts(c + 2, va);          // A stage (c+2)%3
        if (c + 3 < NCH) ldgA(c + 3, vb);

        if (c + 1 < NCH) asm volatile("cp.async.wait_group 1;" ::: "memory");
        else             asm volatile("cp.async.wait_group 0;" ::: "memory");
        __syncthreads();

        const uint32_t AsbU = smem_u32(Abuf + (c % 3) * PV_AST);
        const uint32_t BsbU = smem_u32(Bbuf + (c & 1) * PV_BST);
        #pragma unroll
        for (int ks = 0; ks < 4; ks++) {
            uint32_t af[2][4];
            #pragma unroll
            for (int mt = 0; mt < 2; mt++)
                ldsm4(af[mt], AsbU + ((wm * 32 + mt * 16 + arow) * PV_AROW + ks * 8 + acol) * 4);
            #pragma unroll
            for (int j = 0; j < 4; j++) {
                uint32_t bf[4];
                ldsm4(bf, BsbU + ((wn * 64 + j * 16 + brow) * PV_AROW + ks * 8 + bcol) * 4);
                #pragma unroll
                for (int mt = 0; mt < 2; mt++) {
                    mma_tf32(acc[mt][2 * j + 0], af[mt], bf + 0);
                    mma_tf32(acc[mt][2 * j + 1], af[mt], bf + 2);
                }
            }
        }
        __syncthreads();
        if (c + 2 < NCH) cpB(c + 2);                 // overwrite B stage c&1

        va[0] = vb[0]; va[1] = vb[1];
    }

    // Z reduction
    __syncthreads();
    atomicAdd(&zsm[tr], zp[0]);
    atomicAdd(&zsm[tr + 32], zp[1]);
    __syncthreads();

    const float gam = __ldg(gamma_p);
    #pragma unroll
    for (int mt = 0; mt < 2; mt++) {
        int row0 = wm * 32 + mt * 16 + (lane >> 2);
        float sc0 = gam / zsm[row0];
        float sc1 = gam / zsm[row0 + 8];
        #pragma unroll
        for (int nt = 0; nt < 8; nt++) {
            int col = wn * 64 + nt * 8 + 2 * (lane & 3);
            size_t base = ((size_t)b * Nq + qbase + row0) * C + col;
            float2 x0 = *(const float2*)(x + base);
            float2 o0;
            o0.x = sc0 * acc[mt][nt][0] + x0.x;
            o0.y = sc0 * acc[mt][nt][1] + x0.y;
            *(float2*)(y + base) = o0;
            size_t base2 = base + 8 * (size_t)C;
            float2 x1 = *(const float2*)(x + base2);
            float2 o1;
            o1.x = sc1 * acc[mt][nt][2] + x1.x;
            o1.y = sc1 * acc[mt][nt][3] + x1.y;
            *(float2*)(y + base2) = o1;
        }
    }
}

// ===========================================================================
extern "C" void kernel_launch(void* const* d_in, const int* in_sizes, int n_in,
                              void* d_out, int out_size) {
    (void)in_sizes; (void)n_in; (void)out_size;
    const float* x     = (const float*)d_in[0];
    const float* Wf    = (const float*)d_in[1];
    const float* bf    = (const float*)d_in[2];
    const float* Wg    = (const float*)d_in[3];
    const float* bg    = (const float*)d_in[4];
    const float* Wh    = (const float*)d_in[5];
    const float* bh    = (const float*)d_in[6];
    const float* gamma = (const float*)d_in[7];
    float* y = (float*)d_out;

    cudaFuncSetAttribute(proj_kernel, cudaFuncAttributeMaxDynamicSharedMemorySize, PJ_SMEM);
    cudaFuncSetAttribute(score_kernel, cudaFuncAttributeMaxDynamicSharedMemorySize, SC_SMEM);
    cudaFuncSetAttribute(pv_kernel, cudaFuncAttributeMaxDynamicSharedMemorySize, PV_SMEM);

    wtrans_kernel<<<320, 256>>>(Wf, Wg, Wh);
    proj_kernel<<<(Bb * Nq) / 64, 256, PJ_SMEM>>>(x, bf, bg, bh);
    score_kernel<<<dim3(Nq / 128, Nq / 128, Bb), 256, SC_SMEM>>>();
    pv_kernel<<<dim3(Nq / 64, Bb), 256, PV_SMEM>>>(gamma, x, y);
}

// round 10
// speedup vs baseline: 1.0462x; 1.0462x over previous
#include <cuda_runtime.h>
#include <cstdint>

// Problem dims (fixed by dataset)
constexpr int Bb = 4;      // batch
constexpr int Nq = 4096;   // H*W
constexpr int C  = 256;    // channels
constexpr int CK = 32;     // key/query channels

// Scratch in __device__ globals (allocation-free rule)
__device__ float g_f [(size_t)Bb * Nq * CK];             // keys   (tf32 hi)
__device__ float g_fl[(size_t)Bb * Nq * CK];             // keys   (lo residual)
__device__ float g_g [(size_t)Bb * Nq * CK];             // queries(tf32 hi)
__device__ float g_gl[(size_t)Bb * Nq * CK];             // queries(lo residual)
__device__ float g_hT[(size_t)Bb * C * Nq];              // values, transposed, tf32-rounded
__device__ float g_s [(size_t)Bb * Nq * Nq];             // raw scores (256 MB)
__device__ float g_WT  [320 * 256];                      // [Wf|Wg|Wh]^T, tf32 hi
__device__ float g_WTlo[64 * 256];                       // lo residual for f,g cols

__device__ __forceinline__ uint32_t smem_u32(const void* p) {
    return (uint32_t)__cvta_generic_to_shared(p);
}
__device__ __forceinline__ void cp16(uint32_t s, const void* g) {
    asm volatile("cp.async.cg.shared.global [%0], [%1], 16;" :: "r"(s), "l"(g));
}
__device__ __forceinline__ void cp_commit() {
    asm volatile("cp.async.commit_group;" ::: "memory");
}
__device__ __forceinline__ uint32_t f2tf32(float f) {
    uint32_t u;
    asm("cvt.rna.tf32.f32 %0, %1;" : "=r"(u) : "f"(f));
    return u;
}
__device__ __forceinline__ void mma_tf32(float* d, const uint32_t* a, const uint32_t* bfr) {
    asm volatile(
        "mma.sync.aligned.m16n8k8.row.col.f32.tf32.tf32.f32 "
        "{%0,%1,%2,%3}, {%4,%5,%6,%7}, {%8,%9}, {%0,%1,%2,%3};"
        : "+f"(d[0]), "+f"(d[1]), "+f"(d[2]), "+f"(d[3])
        : "r"(a[0]), "r"(a[1]), "r"(a[2]), "r"(a[3]), "r"(bfr[0]), "r"(bfr[1]));
}
__device__ __forceinline__ void ldsm4(uint32_t* r, uint32_t a) {
    asm volatile("ldmatrix.sync.aligned.m8n8.x4.shared.b16 {%0,%1,%2,%3}, [%4];"
        : "=r"(r[0]), "=r"(r[1]), "=r"(r[2]), "=r"(r[3]) : "r"(a));
}
__device__ __forceinline__ void ldsm2(uint32_t* r, uint32_t a) {
    asm volatile("ldmatrix.sync.aligned.m8n8.x2.shared.b16 {%0,%1}, [%2];"
        : "=r"(r[0]), "=r"(r[1]) : "r"(a));
}

// ===========================================================================
// Kernel 0: W pre-transpose + tf32 hi/lo pre-split (one-shot, tiny)
// ===========================================================================
__global__ void wtrans_kernel(const float* __restrict__ Wf,
                              const float* __restrict__ Wg,
                              const float* __restrict__ Wh) {
    int idx = blockIdx.x * 256 + threadIdx.x;       // 320*256 total
    int n = idx >> 8, k = idx & 255;
    float w;
    if (n < 32)       w = Wf[k * CK + n];
    else if (n < 64)  w = Wg[k * CK + (n - 32)];
    else              w = Wh[k * C + (n - 64)];
    uint32_t hi = f2tf32(w);
    g_WT[n * 256 + k] = __uint_as_float(hi);
    if (n < 64)
        g_WTlo[n * 256 + k] = __uint_as_float(f2tf32(w - __uint_as_float(hi)));
}

// ===========================================================================
// Kernel 1: fused projections via ldmatrix + tensor cores. (unchanged R8)
// ===========================================================================
constexpr int PJ_SMEM = (64 * 36 + 320 * 36 + 64 * 36) * 4;   // 64,512 B

__global__ __launch_bounds__(256, 2)
void proj_kernel(const float* __restrict__ x,
                 const float* __restrict__ bfv, const float* __restrict__ bgv,
                 const float* __restrict__ bhv) {
    extern __shared__ float sm[];
    float* Xs  = sm;                   // [64][36]
    float* Whs = sm + 64 * 36;         // [320][36]
    float* Wls = sm + 64 * 36 + 320 * 36;  // [64][36]

    const int t = threadIdx.x;
    const int lane = t & 31, wid = t >> 5;
    const int wm = wid >> 2, wn = wid & 3;
    const int rowbase = blockIdx.x * 64;

    const int arow = (lane & 7) + ((lane >> 3) & 1) * 8;
    const int acol = (lane >> 4) * 4;
    const int brow2 = lane & 7;
    const int bcol2 = ((lane >> 3) & 1) * 4;

    const uint32_t XsU = smem_u32(Xs), WhU = smem_u32(Whs), WlU = smem_u32(Wls);

    float acc[2][10][4] = {};

    for (int ch = 0; ch < 8; ch++) {
        const int k0 = ch * 32;
        __syncthreads();
        #pragma unroll
        for (int i = 0; i < 2; i++) {
            int idx = t + i * 256;
            int r = idx >> 3, c4 = (idx & 7) * 4;
            cp16(XsU + (r * 36 + c4) * 4, x + (size_t)(rowbase + r) * C + k0 + c4);
        }
        #pragma unroll
        for (int i = 0; i < 10; i++) {
            int idx = t + i * 256;
            int r = idx >> 3, c4 = (idx & 7) * 4;
            cp16(WhU + (r * 36 + c4) * 4, g_WT + r * 256 + k0 + c4);
        }
        #pragma unroll
        for (int i = 0; i < 2; i++) {
            int idx = t + i * 256;
            int r = idx >> 3, c4 = (idx & 7) * 4;
            cp16(WlU + (r * 36 + c4) * 4, g_WTlo + r * 256 + k0 + c4);
        }
        cp_commit();
        asm volatile("cp.async.wait_group 0;" ::: "memory");
        __syncthreads();

        #pragma unroll
        for (int ks = 0; ks < 4; ks++) {
            uint32_t xr[2][4], ah[2][4], al[2][4];
            #pragma unroll
            for (int mt = 0; mt < 2; mt++) {
                ldsm4(xr[mt], XsU + ((wm * 32 + mt * 16 + arow) * 36 + ks * 8 + acol) * 4);
                #pragma unroll
                for (int e = 0; e < 4; e++) {
                    float v = __uint_as_float(xr[mt][e]);
                    ah[mt][e] = f2tf32(v);
                    al[mt][e] = f2tf32(v - __uint_as_float(ah[mt][e]));
                }
            }
            #pragma unroll
            for (int nt = 0; nt < 10; nt++) {
                const int c0 = nt * 32 + wn * 8;
                uint32_t bh[2];
                ldsm2(bh, WhU + ((c0 + brow2) * 36 + ks * 8 + bcol2) * 4);
                if (nt < 2) {
                    uint32_t bl[2];
                    ldsm2(bl, WlU + ((c0 + brow2) * 36 + ks * 8 + bcol2) * 4);
                    #pragma unroll
                    for (int mt = 0; mt < 2; mt++) {
                        mma_tf32(acc[mt][nt], ah[mt], bh);
                        mma_tf32(acc[mt][nt], ah[mt], bl);
                        mma_tf32(acc[mt][nt], al[mt], bh);
                    }
                } else {
                    #pragma unroll
                    for (int mt = 0; mt < 2; mt++)
                        mma_tf32(acc[mt][nt], ah[mt], bh);
                }
            }
        }
    }

    #pragma unroll
    for (int nt = 0; nt < 10; nt++) {
        const int c0 = nt * 32 + wn * 8 + 2 * (lane & 3);
        #pragma unroll
        for (int mt = 0; mt < 2; mt++) {
            const int r0 = rowbase + wm * 32 + mt * 16 + (lane >> 2);
            #pragma unroll
            for (int h = 0; h < 2; h++) {
                const int r = r0 + h * 8;
                const float d0 = acc[mt][nt][h * 2 + 0];
                const float d1 = acc[mt][nt][h * 2 + 1];
                if (nt == 0) {
                    float v0 = d0 + bfv[c0], v1 = d1 + bfv[c0 + 1];
                    uint32_t h0 = f2tf32(v0), h1 = f2tf32(v1);
                    float2 oh; oh.x = __uint_as_float(h0); oh.y = __uint_as_float(h1);
                    float2 ol;
                    ol.x = __uint_as_float(f2tf32(v0 - oh.x));
                    ol.y = __uint_as_float(f2tf32(v1 - oh.y));
                    *(float2*)(g_f  + (size_t)r * CK + c0) = oh;
                    *(float2*)(g_fl + (size_t)r * CK + c0) = ol;
                } else if (nt == 1) {
                    int c = c0 - 32;
                    float v0 = d0 + bgv[c], v1 = d1 + bgv[c + 1];
                    uint32_t h0 = f2tf32(v0), h1 = f2tf32(v1);
                    float2 oh; oh.x = __uint_as_float(h0); oh.y = __uint_as_float(h1);
                    float2 ol;
                    ol.x = __uint_as_float(f2tf32(v0 - oh.x));
                    ol.y = __uint_as_float(f2tf32(v1 - oh.y));
                    *(float2*)(g_g  + (size_t)r * CK + c) = oh;
                    *(float2*)(g_gl + (size_t)r * CK + c) = ol;
                } else {
                    int c = c0 - 64;
                    int bb = r >> 12, n = r & 4095;
                    g_hT[((size_t)bb * C + c) * Nq + n] =
                        __uint_as_float(f2tf32(d0 + bhv[c]));
                    g_hT[((size_t)bb * C + c + 1) * Nq + n] =
                        __uint_as_float(f2tf32(d1 + bhv[c + 1]));
                }
            }
        }
    }
}

// ===========================================================================
// Kernel 2: scores, pre-split hi/lo inputs -> pure LDSM + HMMA loop. (R8)
// ===========================================================================
constexpr int SC_SMEM = 4 * 128 * 36 * 4;   // 73,728 B

__global__ __launch_bounds__(256)
void score_kernel() {
    extern __shared__ float sm[];
    float* Gh = sm;
    float* Gl = sm + 4608;
    float* Fh = sm + 9216;
    float* Fl = sm + 13824;

    const int t = threadIdx.x;
    const int lane = t & 31, wid = t >> 5;
    const int wm = wid >> 2, wn = wid & 3;
    const int mbase = blockIdx.y * 128, nbase = blockIdx.x * 128;
    const size_t zoff = (size_t)blockIdx.z * Nq * CK;

    #pragma unroll
    for (int i = 0; i < 4; i++) {
        int idx = t + i * 256;
        int r = idx >> 3, c4 = (idx & 7) * 4;
        *(float4*)(Gh + r * 36 + c4) = *(const float4*)(g_g  + zoff + (size_t)(mbase + r) * CK + c4);
        *(float4*)(Gl + r * 36 + c4) = *(const float4*)(g_gl + zoff + (size_t)(mbase + r) * CK + c4);
        *(float4*)(Fh + r * 36 + c4) = *(const float4*)(g_f  + zoff + (size_t)(nbase + r) * CK + c4);
        *(float4*)(Fl + r * 36 + c4) = *(const float4*)(g_fl + zoff + (size_t)(nbase + r) * CK + c4);
    }
    __syncthreads();

    const int arow = (lane & 7) + ((lane >> 3) & 1) * 8;
    const int acol = (lane >> 4) * 4;
    const int brow = (lane >> 4) * 8 + (lane & 7);
    const int bcol = ((lane >> 3) & 1) * 4;
    const uint32_t GhU = smem_u32(Gh), GlU = smem_u32(Gl);
    const uint32_t FhU = smem_u32(Fh), FlU = smem_u32(Fl);

    float acc[4][4][4] = {};
    #pragma unroll
    for (int ks = 0; ks < 4; ks++) {
        uint32_t ah[4][4], al[4][4];
        #pragma unroll
        for (int mt = 0; mt < 4; mt++) {
            uint32_t off = ((wm * 64 + mt * 16 + arow) * 36 + ks * 8 + acol) * 4;
            ldsm4(ah[mt], GhU + off);
            ldsm4(al[mt], GlU + off);
        }
        #pragma unroll
        for (int j = 0; j < 2; j++) {
            uint32_t bh[4], bl[4];
            uint32_t off = ((wn * 32 + j * 16 + brow) * 36 + ks * 8 + bcol) * 4;
            ldsm4(bh, FhU + off);
            ldsm4(bl, FlU + off);
            #pragma unroll
            for (int sub = 0; sub < 2; sub++) {
                #pragma unroll
                for (int mt = 0; mt < 4; mt++) {
                    mma_tf32(acc[mt][2 * j + sub], ah[mt], bh + sub * 2);
                    mma_tf32(acc[mt][2 * j + sub], ah[mt], bl + sub * 2);
                    mma_tf32(acc[mt][2 * j + sub], al[mt], bh + sub * 2);
                }
            }
        }
    }

    float* sout = g_s + (size_t)blockIdx.z * Nq * Nq;
    #pragma unroll
    for (int mt = 0; mt < 4; mt++) {
        int r0 = mbase + wm * 64 + mt * 16 + (lane >> 2);
        #pragma unroll
        for (int nt = 0; nt < 4; nt++) {
            int col = nbase + wn * 32 + nt * 8 + 2 * (lane & 3);
            float2 o0; o0.x = acc[mt][nt][0]; o0.y = acc[mt][nt][1];
            *(float2*)(sout + (size_t)r0 * Nq + col) = o0;
            float2 o1; o1.x = acc[mt][nt][2]; o1.y = acc[mt][nt][3];
            *(float2*)(sout + (size_t)(r0 + 8) * Nq + col) = o1;
        }
    }
}

// ===========================================================================
// Kernel 3: fused exp-softmax + PV + residual.
//   CTA 128(q) x 256(C), 256 threads, 8 warps (2m x 4n), WARP TILE 64x64.
//   Halves smem fragment re-reads vs R8 (crossbar was co-binding with tensor):
//   reads/chunk = 8 warps x (A 8KB + B 8KB) = 128KB < tensor floor.
//   A: 3-stage exp->STS pipeline; B: 4-stage cp.async.
// ===========================================================================
constexpr int PV_AROW = 36;
constexpr int PV_AST  = 128 * PV_AROW;             // 4608 floats
constexpr int PV_BST  = 256 * PV_AROW;             // 9216 floats
constexpr int PV_SMEM = (3 * PV_AST + 4 * PV_BST + 128) * 4;   // 203,776 B
constexpr int NCH = Nq / 32;                       // 128

__global__ __launch_bounds__(256, 1)
void pv_kernel(const float* __restrict__ gamma_p,
               const float* __restrict__ x, float* __restrict__ y) {
    extern __shared__ float sm[];
    float* Abuf = sm;
    float* Bbuf = sm + 3 * PV_AST;
    float* zsm  = sm + 3 * PV_AST + 4 * PV_BST;

    const int t = threadIdx.x;
    const int lane = t & 31, wid = t >> 5;
    const int wm = wid >> 2, wn = wid & 3;         // 2(M) x 4(N)
    const int qbase = blockIdx.x * 128;
    const int b = blockIdx.y;
    const float* Pm  = g_s  + (size_t)b * Nq * Nq;
    const float* hTb = g_hT + (size_t)b * C * Nq;

    if (t < 128) zsm[t] = 0.f;

    const int tr  = t >> 3;          // 0..31
    const int tc4 = (t & 7) * 4;

    const int arow = (lane & 7) + ((lane >> 3) & 1) * 8;
    const int acol = (lane >> 4) * 4;
    const int brow = (lane >> 4) * 8 + (lane & 7);
    const int bcol = ((lane >> 3) & 1) * 4;

    float4 va[4], vb[4];
    float zp[4] = {0.f, 0.f, 0.f, 0.f};

    auto ldgA = [&](int chunk, float4* v) {
        const float* base = Pm + (size_t)(qbase + tr) * Nq + chunk * 32 + tc4;
        #pragma unroll
        for (int i = 0; i < 4; i++)
            v[i] = *(const float4*)(base + (size_t)(32 * i) * Nq);
    };
    auto expSts = [&](int chunk, const float4* v) {
        float* Ad = Abuf + (chunk % 3) * PV_AST;
        #pragma unroll
        for (int i = 0; i < 4; i++) {
            float4 p;
            p.x = __uint_as_float(f2tf32(__expf(v[i].x)));
            p.y = __uint_as_float(f2tf32(__expf(v[i].y)));
            p.z = __uint_as_float(f2tf32(__expf(v[i].z)));
            p.w = __uint_as_float(f2tf32(__expf(v[i].w)));
            zp[i] += (p.x + p.y) + (p.z + p.w);
            *(float4*)(Ad + (tr + 32 * i) * PV_AROW + tc4) = p;
        }
    };
    auto cpB = [&](int chunk) {
        float* Bd = Bbuf + (chunk & 3) * PV_BST;
        #pragma unroll
        for (int i = 0; i < 8; i++) {
            int idx = t + i * 256;
            int r = idx >> 3, c4 = (idx & 7) * 4;
            cp16(smem_u32(Bd + r * PV_AROW + c4),
                 hTb + (size_t)r * Nq + chunk * 32 + c4);
        }
        cp_commit();
    };

    cpB(0); cpB(1); cpB(2);
    ldgA(0, va);
    expSts(0, va);
    ldgA(1, va);

    float acc[4][8][4] = {};   // warp tile 64(M) x 64(N)

    for (int c = 0; c < NCH; c++) {
        if (c + 1 < NCH) expSts(c + 1, va);
        if (c + 2 < NCH) ldgA(c + 2, vb);

        int pend = NCH - 1 - c;
        if (pend >= 2)      asm volatile("cp.async.wait_group 2;" ::: "memory");
        else if (pend == 1) asm volatile("cp.async.wait_group 1;" ::: "memory");
        else                asm volatile("cp.async.wait_group 0;" ::: "memory");
        __syncthreads();

        if (c + 3 < NCH) cpB(c + 3);

        const uint32_t AsbU = smem_u32(Abuf + (c % 3) * PV_AST);
        const uint32_t BsbU = smem_u32(Bbuf + (c & 3) * PV_BST);
        #pragma unroll
        for (int ks = 0; ks < 4; ks++) {
            uint32_t af[4][4];
            #pragma unroll
            for (int mt = 0; mt < 4; mt++)
                ldsm4(af[mt], AsbU + ((wm * 64 + mt * 16 + arow) * PV_AROW + ks * 8 + acol) * 4);
            #pragma unroll
            for (int j = 0; j < 4; j++) {
                uint32_t bf[4];
                ldsm4(bf, BsbU + ((wn * 64 + j * 16 + brow) * PV_AROW + ks * 8 + bcol) * 4);
                #pragma unroll
                for (int mt = 0; mt < 4; mt++) {
                    mma_tf32(acc[mt][2 * j + 0], af[mt], bf + 0);
                    mma_tf32(acc[mt][2 * j + 1], af[mt], bf + 2);
                }
            }
        }

        #pragma unroll
        for (int i = 0; i < 4; i++) va[i] = vb[i];
    }

    __syncthreads();
    #pragma unroll
    for (int i = 0; i < 4; i++) atomicAdd(&zsm[tr + 32 * i], zp[i]);
    __syncthreads();

    const float gam = __ldg(gamma_p);
    #pragma unroll
    for (int mt = 0; mt < 4; mt++) {
        int row0 = wm * 64 + mt * 16 + (lane >> 2);
        float sc0 = gam / zsm[row0];
        float sc1 = gam / zsm[row0 + 8];
        #pragma unroll
        for (int nt = 0; nt < 8; nt++) {
            int col = wn * 64 + nt * 8 + 2 * (lane & 3);
            size_t base = ((size_t)b * Nq + qbase + row0) * C + col;
            float2 x0 = *(const float2*)(x + base);
            float2 o0;
            o0.x = sc0 * acc[mt][nt][0] + x0.x;
            o0.y = sc0 * acc[mt][nt][1] + x0.y;
            *(float2*)(y + base) = o0;
            size_t base2 = base + 8 * (size_t)C;
            float2 x1 = *(const float2*)(x + base2);
            float2 o1;
            o1.x = sc1 * acc[mt][nt][2] + x1.x;
            o1.y = sc1 * acc[mt][nt][3] + x1.y;
            *(float2*)(y + base2) = o1;
        }
    }
}

// ===========================================================================
extern "C" void kernel_launch(void* const* d_in, const int* in_sizes, int n_in,
                              void* d_out, int out_size) {
    (void)in_sizes; (void)n_in; (void)out_size;
    const float* x     = (const float*)d_in[0];
    const float* Wf    = (const float*)d_in[1];
    const float* bf    = (const float*)d_in[2];
    const float* Wg    = (const float*)d_in[3];
    const float* bg    = (const float*)d_in[4];
    const float* Wh    = (const float*)d_in[5];
    const float* bh    = (const float*)d_in[6];
    const float* gamma = (const float*)d_in[7];
    float* y = (float*)d_out;

    cudaFuncSetAttribute(proj_kernel, cudaFuncAttributeMaxDynamicSharedMemorySize, PJ_SMEM);
    cudaFuncSetAttribute(score_kernel, cudaFuncAttributeMaxDynamicSharedMemorySize, SC_SMEM);
    cudaFuncSetAttribute(pv_kernel, cudaFuncAttributeMaxDynamicSharedMemorySize, PV_SMEM);

    wtrans_kernel<<<320, 256>>>(Wf, Wg, Wh);
    proj_kernel<<<(Bb * Nq) / 64, 256, PJ_SMEM>>>(x, bf, bg, bh);
    score_kernel<<<dim3(Nq / 128, Nq / 128, Bb), 256, SC_SMEM>>>();
    pv_kernel<<<dim3(Nq / 128, Bb), 256, PV_SMEM>>>(gamma, x, y);
}

// round 11
// speedup vs baseline: 1.4873x; 1.4216x over previous
#include <cuda_runtime.h>
#include <cuda_fp16.h>
#include <cstdint>

// Problem dims (fixed by dataset)
constexpr int Bb = 4;      // batch
constexpr int Nq = 4096;   // H*W
constexpr int C  = 256;    // channels
constexpr int CK = 32;     // key/query channels

// Scratch in __device__ globals (allocation-free rule)
__device__ __half g_f [(size_t)Bb * Nq * CK];            // keys   (fp16 hi)
__device__ __half g_fl[(size_t)Bb * Nq * CK];            // keys   (fp16 lo residual)
__device__ __half g_g [(size_t)Bb * Nq * CK];            // queries(fp16 hi)
__device__ __half g_gl[(size_t)Bb * Nq * CK];            // queries(fp16 lo residual)
__device__ __half g_hT[(size_t)Bb * C * Nq];             // values, transposed, fp16
__device__ float  g_s [(size_t)Bb * Nq * Nq];            // raw scores fp32 (256 MB)
__device__ __half g_WT  [320 * 256];                     // [Wf|Wg|Wh]^T fp16 hi
__device__ __half g_WTlo[64 * 256];                      // lo residual for f,g cols
__device__ unsigned int g_rowmaxE[Bb * Nq];              // encoded row maxes

__device__ __forceinline__ uint32_t smem_u32(const void* p) {
    return (uint32_t)__cvta_generic_to_shared(p);
}
__device__ __forceinline__ void cp16(uint32_t s, const void* g) {
    asm volatile("cp.async.cg.shared.global [%0], [%1], 16;" :: "r"(s), "l"(g));
}
__device__ __forceinline__ void cp_commit() {
    asm volatile("cp.async.commit_group;" ::: "memory");
}
__device__ __forceinline__ uint32_t pack2(__half a, __half b) {
    __half2 h = __halves2half2(a, b);
    return *(uint32_t*)&h;
}
__device__ __forceinline__ void mma_f16(float* d, const uint32_t* a, const uint32_t* b) {
    asm volatile(
        "mma.sync.aligned.m16n8k16.row.col.f32.f16.f16.f32 "
        "{%0,%1,%2,%3}, {%4,%5,%6,%7}, {%8,%9}, {%0,%1,%2,%3};"
        : "+f"(d[0]), "+f"(d[1]), "+f"(d[2]), "+f"(d[3])
        : "r"(a[0]), "r"(a[1]), "r"(a[2]), "r"(a[3]), "r"(b[0]), "r"(b[1]));
}
__device__ __forceinline__ void ldsm4(uint32_t* r, uint32_t a) {
    asm volatile("ldmatrix.sync.aligned.m8n8.x4.shared.b16 {%0,%1,%2,%3}, [%4];"
        : "=r"(r[0]), "=r"(r[1]), "=r"(r[2]), "=r"(r[3]) : "r"(a));
}
__device__ __forceinline__ void ldsm2(uint32_t* r, uint32_t a) {
    asm volatile("ldmatrix.sync.aligned.m8n8.x2.shared.b16 {%0,%1}, [%2];"
        : "=r"(r[0]), "=r"(r[1]) : "r"(a));
}
// monotone float<->uint encoding for atomicMax over signed floats
__device__ __forceinline__ uint32_t fenc(float f) {
    uint32_t u = __float_as_uint(f);
    return (u & 0x80000000u) ? ~u : (u | 0x80000000u);
}
__device__ __forceinline__ float fdec(uint32_t e) {
    uint32_t u = (e & 0x80000000u) ? (e & 0x7fffffffu) : ~e;
    return __uint_as_float(u);
}

// ===========================================================================
// Kernel 0: W pre-transpose + fp16 hi/lo pre-split; init row-max table.
// ===========================================================================
__global__ void wtrans_kernel(const float* __restrict__ Wf,
                              const float* __restrict__ Wg,
                              const float* __restrict__ Wh) {
    int idx = blockIdx.x * 256 + threadIdx.x;       // 320*256 total
    if (idx < Bb * Nq) g_rowmaxE[idx] = 0u;         // < any real encoded value
    int n = idx >> 8, k = idx & 255;
    float w;
    if (n < 32)       w = Wf[k * CK + n];
    else if (n < 64)  w = Wg[k * CK + (n - 32)];
    else              w = Wh[k * C + (n - 64)];
    __half hi = __float2half_rn(w);
    g_WT[n * 256 + k] = hi;
    if (n < 64)
        g_WTlo[n * 256 + k] = __float2half_rn(w - __half2float(hi));
}

// ===========================================================================
// Kernel 1: fused projections, fp16 mma. CTA 64 rows x 320 cols, K=256.
// f,g (nt 0,1): 3-term hi/lo; h (nt>=2): single fp16.
// smem pitch 80B/row (40 halves).
// ===========================================================================
constexpr int XH_OFF = 0;          // 64*80   = 5120
constexpr int XL_OFF = 5120;       // 5120
constexpr int WH_OFF = 10240;      // 320*80  = 25600
constexpr int WL_OFF = 35840;      // 64*80   = 5120
constexpr int PJ_SMEM = 40960;

__global__ __launch_bounds__(256, 2)
void proj_kernel(const float* __restrict__ x,
                 const float* __restrict__ bfv, const float* __restrict__ bgv,
                 const float* __restrict__ bhv) {
    extern __shared__ char dsm[];
    const uint32_t base = smem_u32(dsm);

    const int t = threadIdx.x;
    const int lane = t & 31, wid = t >> 5;
    const int wm = wid >> 2, wn = wid & 3;
    const int rowbase = blockIdx.x * 64;

    const int arow   = (lane & 7) + ((lane >> 3) & 1) * 8;
    const int acol16 = (lane >> 4) * 16;
    const int brow2  = lane & 7;
    const int bcol16 = ((lane >> 3) & 1) * 16;

    float acc[2][10][4] = {};
    float4 va[2], vb[2];

    auto ldgX = [&](int ch, float4* v) {
        #pragma unroll
        for (int i = 0; i < 2; i++) {
            int idx = t + i * 256;
            int r = idx >> 3, c4 = (idx & 7) * 4;
            v[i] = *(const float4*)(x + (size_t)(rowbase + r) * C + ch * 32 + c4);
        }
    };
    auto stsX = [&](const float4* v) {
        #pragma unroll
        for (int i = 0; i < 2; i++) {
            int idx = t + i * 256;
            int r = idx >> 3, c4 = (idx & 7) * 4;
            float f[4] = {v[i].x, v[i].y, v[i].z, v[i].w};
            __half h[4], l[4];
            #pragma unroll
            for (int e = 0; e < 4; e++) {
                h[e] = __float2half_rn(f[e]);
                l[e] = __float2half_rn(f[e] - __half2float(h[e]));
            }
            uint2 uh, ul;
            uh.x = pack2(h[0], h[1]); uh.y = pack2(h[2], h[3]);
            ul.x = pack2(l[0], l[1]); ul.y = pack2(l[2], l[3]);
            *(uint2*)(dsm + XH_OFF + r * 80 + c4 * 2) = uh;
            *(uint2*)(dsm + XL_OFF + r * 80 + c4 * 2) = ul;
        }
    };

    ldgX(0, va);
    for (int ch = 0; ch < 8; ch++) {
        __syncthreads();            // prev chunk's mma reads done
        stsX(va);
        if (ch < 7) ldgX(ch + 1, vb);
        #pragma unroll
        for (int i = 0; i < 5; i++) {          // W hi: 1280 cp16
            int idx = t + i * 256;
            int r = idx >> 2, seg = idx & 3;
            cp16(base + WH_OFF + r * 80 + seg * 16, g_WT + r * 256 + ch * 32 + seg * 8);
        }
        {
            int r = t >> 2, seg = t & 3;       // W lo: 256 cp16
            cp16(base + WL_OFF + r * 80 + seg * 16, g_WTlo + r * 256 + ch * 32 + seg * 8);
        }
        cp_commit();
        asm volatile("cp.async.wait_group 0;" ::: "memory");
        __syncthreads();

        #pragma unroll
        for (int ks = 0; ks < 2; ks++) {
            uint32_t ah[2][4], al[2][4];
            #pragma unroll
            for (int mt = 0; mt < 2; mt++) {
                uint32_t off = (wm * 32 + mt * 16 + arow) * 80 + ks * 32 + acol16;
                ldsm4(ah[mt], base + XH_OFF + off);
                ldsm4(al[mt], base + XL_OFF + off);
            }
            #pragma unroll
            for (int nt = 0; nt < 10; nt++) {
                const int c0 = nt * 32 + wn * 8;
                uint32_t off = (c0 + brow2) * 80 + ks * 32 + bcol16;
                uint32_t bh[2];
                ldsm2(bh, base + WH_OFF + off);
                if (nt < 2) {
                    uint32_t bl[2];
                    ldsm2(bl, base + WL_OFF + off);
                    #pragma unroll
                    for (int mt = 0; mt < 2; mt++) {
                        mma_f16(acc[mt][nt], ah[mt], bh);
                        mma_f16(acc[mt][nt], ah[mt], bl);
                        mma_f16(acc[mt][nt], al[mt], bh);
                    }
                } else {
                    #pragma unroll
                    for (int mt = 0; mt < 2; mt++)
                        mma_f16(acc[mt][nt], ah[mt], bh);
                }
            }
        }
        va[0] = vb[0]; va[1] = vb[1];
    }

    // epilogue
    #pragma unroll
    for (int nt = 0; nt < 10; nt++) {
        const int c0 = nt * 32 + wn * 8 + 2 * (lane & 3);
        #pragma unroll
        for (int mt = 0; mt < 2; mt++) {
            const int r0 = rowbase + wm * 32 + mt * 16 + (lane >> 2);
            #pragma unroll
            for (int h2 = 0; h2 < 2; h2++) {
                const int r = r0 + h2 * 8;
                const float d0 = acc[mt][nt][h2 * 2 + 0];
                const float d1 = acc[mt][nt][h2 * 2 + 1];
                if (nt == 0) {
                    float v0 = d0 + bfv[c0], v1 = d1 + bfv[c0 + 1];
                    __half a0 = __float2half_rn(v0), a1 = __float2half_rn(v1);
                    __half b0 = __float2half_rn(v0 - __half2float(a0));
                    __half b1 = __float2half_rn(v1 - __half2float(a1));
                    *(uint32_t*)(g_f  + (size_t)r * CK + c0) = pack2(a0, a1);
                    *(uint32_t*)(g_fl + (size_t)r * CK + c0) = pack2(b0, b1);
                } else if (nt == 1) {
                    int c = c0 - 32;
                    float v0 = d0 + bgv[c], v1 = d1 + bgv[c + 1];
                    __half a0 = __float2half_rn(v0), a1 = __float2half_rn(v1);
                    __half b0 = __float2half_rn(v0 - __half2float(a0));
                    __half b1 = __float2half_rn(v1 - __half2float(a1));
                    *(uint32_t*)(g_g  + (size_t)r * CK + c) = pack2(a0, a1);
                    *(uint32_t*)(g_gl + (size_t)r * CK + c) = pack2(b0, b1);
                } else {
                    int c = c0 - 64;
                    int bb = r >> 12, n = r & 4095;
                    g_hT[((size_t)bb * C + c) * Nq + n]     = __float2half_rn(d0 + bhv[c]);
                    g_hT[((size_t)bb * C + c + 1) * Nq + n] = __float2half_rn(d1 + bhv[c + 1]);
                }
            }
        }
    }
}

// ===========================================================================
// Kernel 2: scores via fp16 3-term hi/lo (fp32-grade) + per-row max.
// CTA 128x128, 8 warps (2m x 4n), warp 64x32. K=32 -> 2 K16 steps.
// ===========================================================================
constexpr int GH_OFF = 0, GL_OFF = 10240, FH_OFF = 20480, FL_OFF = 30720;
constexpr int SC_SMEM = 40960;

__global__ __launch_bounds__(256)
void score_kernel() {
    extern __shared__ char dsm[];
    const uint32_t base = smem_u32(dsm);

    const int t = threadIdx.x;
    const int lane = t & 31, wid = t >> 5;
    const int wm = wid >> 2, wn = wid & 3;
    const int mbase = blockIdx.y * 128, nbase = blockIdx.x * 128;
    const int bz = blockIdx.z;
    const size_t zoff = (size_t)bz * Nq * CK;

    #pragma unroll
    for (int i = 0; i < 2; i++) {
        int idx = t + i * 256;
        int r = idx >> 2, seg = idx & 3;
        uint32_t so = r * 80 + seg * 16;
        cp16(base + GH_OFF + so, g_g  + zoff + (size_t)(mbase + r) * CK + seg * 8);
        cp16(base + GL_OFF + so, g_gl + zoff + (size_t)(mbase + r) * CK + seg * 8);
        cp16(base + FH_OFF + so, g_f  + zoff + (size_t)(nbase + r) * CK + seg * 8);
        cp16(base + FL_OFF + so, g_fl + zoff + (size_t)(nbase + r) * CK + seg * 8);
    }
    cp_commit();
    asm volatile("cp.async.wait_group 0;" ::: "memory");
    __syncthreads();

    const int arow   = (lane & 7) + ((lane >> 3) & 1) * 8;
    const int acol16 = (lane >> 4) * 16;
    const int brow   = (lane >> 4) * 8 + (lane & 7);
    const int bcol16 = ((lane >> 3) & 1) * 16;

    float acc[4][4][4] = {};
    #pragma unroll
    for (int ks = 0; ks < 2; ks++) {
        uint32_t ah[4][4], al[4][4];
        #pragma unroll
        for (int mt = 0; mt < 4; mt++) {
            uint32_t off = (wm * 64 + mt * 16 + arow) * 80 + ks * 32 + acol16;
            ldsm4(ah[mt], base + GH_OFF + off);
            ldsm4(al[mt], base + GL_OFF + off);
        }
        #pragma unroll
        for (int j = 0; j < 2; j++) {
            uint32_t bh[4], bl[4];
            uint32_t off = (wn * 32 + j * 16 + brow) * 80 + ks * 32 + bcol16;
            ldsm4(bh, base + FH_OFF + off);
            ldsm4(bl, base + FL_OFF + off);
            #pragma unroll
            for (int sub = 0; sub < 2; sub++) {
                #pragma unroll
                for (int mt = 0; mt < 4; mt++) {
                    mma_f16(acc[mt][2 * j + sub], ah[mt], bh + sub * 2);
                    mma_f16(acc[mt][2 * j + sub], ah[mt], bl + sub * 2);
                    mma_f16(acc[mt][2 * j + sub], al[mt], bh + sub * 2);
                }
            }
        }
    }

    float* sout = g_s + (size_t)bz * Nq * Nq;
    #pragma unroll
    for (int mt = 0; mt < 4; mt++) {
        int r0 = mbase + wm * 64 + mt * 16 + (lane >> 2);
        float mx0 = -3.4e38f, mx1 = -3.4e38f;
        #pragma unroll
        for (int nt = 0; nt < 4; nt++) {
            int col = nbase + wn * 32 + nt * 8 + 2 * (lane & 3);
            float2 o0; o0.x = acc[mt][nt][0]; o0.y = acc[mt][nt][1];
            *(float2*)(sout + (size_t)r0 * Nq + col) = o0;
            float2 o1; o1.x = acc[mt][nt][2]; o1.y = acc[mt][nt][3];
            *(float2*)(sout + (size_t)(r0 + 8) * Nq + col) = o1;
            mx0 = fmaxf(mx0, fmaxf(o0.x, o0.y));
            mx1 = fmaxf(mx1, fmaxf(o1.x, o1.y));
        }
        mx0 = fmaxf(mx0, __shfl_xor_sync(0xffffffffu, mx0, 1));
        mx0 = fmaxf(mx0, __shfl_xor_sync(0xffffffffu, mx0, 2));
        mx1 = fmaxf(mx1, __shfl_xor_sync(0xffffffffu, mx1, 1));
        mx1 = fmaxf(mx1, __shfl_xor_sync(0xffffffffu, mx1, 2));
        if ((lane & 3) == 0) {
            atomicMax(&g_rowmaxE[bz * Nq + r0],     fenc(mx0));
            atomicMax(&g_rowmaxE[bz * Nq + r0 + 8], fenc(mx1));
        }
    }
}

// ===========================================================================
// Kernel 3: fused softmax + PV (fp16 mma) + residual.
//   p = exp(s - rowmax) in fp16; Z in fp32. CTA 128q x 256C, 8 warps 2m x 4n,
//   warp 64x64. A 3-stage exp pipeline, B 4-stage cp.async. Pitch 80B.
// ===========================================================================
constexpr int PV_A_OFF = 0;          // 3 * 128*80 = 30720
constexpr int PV_B_OFF = 30720;      // 4 * 256*80 = 81920
constexpr int PV_Z_OFF = 112640;     // 128 f32
constexpr int PV_SMEM  = 113152;
constexpr int NCH = Nq / 32;         // 128

__global__ __launch_bounds__(256, 1)
void pv_kernel(const float* __restrict__ gamma_p,
               const float* __restrict__ x, float* __restrict__ y) {
    extern __shared__ char dsm[];
    const uint32_t base = smem_u32(dsm);
    float* zsm = (float*)(dsm + PV_Z_OFF);

    const int t = threadIdx.x;
    const int lane = t & 31, wid = t >> 5;
    const int wm = wid >> 2, wn = wid & 3;
    const int qbase = blockIdx.x * 128;
    const int b = blockIdx.y;
    const float*  Pm  = g_s  + (size_t)b * Nq * Nq;
    const __half* hTb = g_hT + (size_t)b * C * Nq;

    if (t < 128) zsm[t] = 0.f;

    const int tr  = t >> 3;          // 0..31
    const int tc4 = (t & 7) * 4;

    const int arow   = (lane & 7) + ((lane >> 3) & 1) * 8;
    const int acol16 = (lane >> 4) * 16;
    const int brow   = (lane >> 4) * 8 + (lane & 7);
    const int bcol16 = ((lane >> 3) & 1) * 16;

    float rm[4];
    #pragma unroll
    for (int i = 0; i < 4; i++)
        rm[i] = fdec(g_rowmaxE[b * Nq + qbase + tr + 32 * i]);

    float4 va[4], vb[4];
    float zp[4] = {0.f, 0.f, 0.f, 0.f};

    auto ldgA = [&](int chunk, float4* v) {
        const float* bp = Pm + (size_t)(qbase + tr) * Nq + chunk * 32 + tc4;
        #pragma unroll
        for (int i = 0; i < 4; i++)
            v[i] = *(const float4*)(bp + (size_t)(32 * i) * Nq);
    };
    auto expSts = [&](int chunk, const float4* v) {
        char* Ad = dsm + PV_A_OFF + (chunk % 3) * 10240;
        #pragma unroll
        for (int i = 0; i < 4; i++) {
            float p0 = __expf(v[i].x - rm[i]);
            float p1 = __expf(v[i].y - rm[i]);
            float p2 = __expf(v[i].z - rm[i]);
            float p3 = __expf(v[i].w - rm[i]);
            zp[i] += (p0 + p1) + (p2 + p3);
            uint2 u;
            u.x = pack2(__float2half_rn(p0), __float2half_rn(p1));
            u.y = pack2(__float2half_rn(p2), __float2half_rn(p3));
            *(uint2*)(Ad + (tr + 32 * i) * 80 + tc4 * 2) = u;
        }
    };
    auto cpB = [&](int chunk) {
        uint32_t Bd = base + PV_B_OFF + (chunk & 3) * 20480;
        #pragma unroll
        for (int i = 0; i < 4; i++) {
            int idx = t + i * 256;
            int r = idx >> 2, seg = idx & 3;
            cp16(Bd + r * 80 + seg * 16, hTb + (size_t)r * Nq + chunk * 32 + seg * 8);
        }
        cp_commit();
    };

    cpB(0); cpB(1); cpB(2);
    ldgA(0, va);
    expSts(0, va);
    ldgA(1, va);

    float acc[4][8][4] = {};   // warp tile 64(M) x 64(N)

    for (int c = 0; c < NCH; c++) {
        if (c + 1 < NCH) expSts(c + 1, va);
        if (c + 2 < NCH) ldgA(c + 2, vb);

        int pend = NCH - 1 - c;
        if (pend >= 2)      asm volatile("cp.async.wait_group 2;" ::: "memory");
        else if (pend == 1) asm volatile("cp.async.wait_group 1;" ::: "memory");
        else                asm volatile("cp.async.wait_group 0;" ::: "memory");
        __syncthreads();

        if (c + 3 < NCH) cpB(c + 3);

        const uint32_t AsbU = base + PV_A_OFF + (c % 3) * 10240;
        const uint32_t BsbU = base + PV_B_OFF + (c & 3) * 20480;
        #pragma unroll
        for (int ks = 0; ks < 2; ks++) {
            uint32_t af[4][4];
            #pragma unroll
            for (int mt = 0; mt < 4; mt++)
                ldsm4(af[mt], AsbU + (wm * 64 + mt * 16 + arow) * 80 + ks * 32 + acol16);
            #pragma unroll
            for (int j = 0; j < 4; j++) {
                uint32_t bf[4];
                ldsm4(bf, BsbU + (wn * 64 + j * 16 + brow) * 80 + ks * 32 + bcol16);
                #pragma unroll
                for (int mt = 0; mt < 4; mt++) {
                    mma_f16(acc[mt][2 * j + 0], af[mt], bf + 0);
                    mma_f16(acc[mt][2 * j + 1], af[mt], bf + 2);
                }
            }
        }

        #pragma unroll
        for (int i = 0; i < 4; i++) va[i] = vb[i];
    }

    __syncthreads();
    #pragma unroll
    for (int i = 0; i < 4; i++) atomicAdd(&zsm[tr + 32 * i], zp[i]);
    __syncthreads();

    const float gam = __ldg(gamma_p);
    #pragma unroll
    for (int mt = 0; mt < 4; mt++) {
        int row0 = wm * 64 + mt * 16 + (lane >> 2);
        float sc0 = gam / zsm[row0];
        float sc1 = gam / zsm[row0 + 8];
        #pragma unroll
        for (int nt = 0; nt < 8; nt++) {
            int col = wn * 64 + nt * 8 + 2 * (lane & 3);
            size_t bo = ((size_t)b * Nq + qbase + row0) * C + col;
            float2 x0 = *(const float2*)(x + bo);
            float2 o0;
            o0.x = sc0 * acc[mt][nt][0] + x0.x;
            o0.y = sc0 * acc[mt][nt][1] + x0.y;
            *(float2*)(y + bo) = o0;
            size_t bo2 = bo + 8 * (size_t)C;
            float2 x1 = *(const float2*)(x + bo2);
            float2 o1;
            o1.x = sc1 * acc[mt][nt][2] + x1.x;
            o1.y = sc1 * acc[mt][nt][3] + x1.y;
            *(float2*)(y + bo2) = o1;
        }
    }
}

// ===========================================================================
extern "C" void kernel_launch(void* const* d_in, const int* in_sizes, int n_in,
                              void* d_out, int out_size) {
    (void)in_sizes; (void)n_in; (void)out_size;
    const float* x     = (const float*)d_in[0];
    const float* Wf    = (const float*)d_in[1];
    const float* bf    = (const float*)d_in[2];
    const float* Wg    = (const float*)d_in[3];
    const float* bg    = (const float*)d_in[4];
    const float* Wh    = (const float*)d_in[5];
    const float* bh    = (const float*)d_in[6];
    const float* gamma = (const float*)d_in[7];
    float* y = (float*)d_out;

    cudaFuncSetAttribute(proj_kernel, cudaFuncAttributeMaxDynamicSharedMemorySize, PJ_SMEM);
    cudaFuncSetAttribute(score_kernel, cudaFuncAttributeMaxDynamicSharedMemorySize, SC_SMEM);
    cudaFuncSetAttribute(pv_kernel, cudaFuncAttributeMaxDynamicSharedMemorySize, PV_SMEM);

    wtrans_kernel<<<320, 256>>>(Wf, Wg, Wh);
    proj_kernel<<<(Bb * Nq) / 64, 256, PJ_SMEM>>>(x, bf, bg, bh);
    score_kernel<<<dim3(Nq / 128, Nq / 128, Bb), 256, SC_SMEM>>>();
    pv_kernel<<<dim3(Nq / 128, Bb), 256, PV_SMEM>>>(gamma, x, y);
}

// round 12
// speedup vs baseline: 1.5187x; 1.0211x over previous
#include <cuda_runtime.h>
#include <cuda_fp16.h>
#include <cstdint>

// Problem dims (fixed by dataset)
constexpr int Bb = 4;      // batch
constexpr int Nq = 4096;   // H*W
constexpr int C  = 256;    // channels
constexpr int CK = 32;     // key/query channels

// Scratch in __device__ globals (allocation-free rule)
__device__ __half g_f [(size_t)Bb * Nq * CK];            // keys   (fp16 hi)
__device__ __half g_fl[(size_t)Bb * Nq * CK];            // keys   (fp16 lo residual)
__device__ __half g_g [(size_t)Bb * Nq * CK];            // queries(fp16 hi)
__device__ __half g_gl[(size_t)Bb * Nq * CK];            // queries(fp16 lo residual)
__device__ __half g_hT[(size_t)Bb * C * Nq];             // values, transposed, fp16
__device__ float  g_s [(size_t)Bb * Nq * Nq];            // raw scores fp32 (256 MB)
__device__ __half g_WT  [320 * 256];                     // [Wf|Wg|Wh]^T fp16 hi
__device__ __half g_WTlo[64 * 256];                      // lo residual for f,g cols
__device__ unsigned int g_rowmaxE[Bb * Nq];              // encoded row maxes

__device__ __forceinline__ uint32_t smem_u32(const void* p) {
    return (uint32_t)__cvta_generic_to_shared(p);
}
__device__ __forceinline__ void cp16(uint32_t s, const void* g) {
    asm volatile("cp.async.cg.shared.global [%0], [%1], 16;" :: "r"(s), "l"(g));
}
__device__ __forceinline__ void cp_commit() {
    asm volatile("cp.async.commit_group;" ::: "memory");
}
__device__ __forceinline__ uint32_t pack2(__half a, __half b) {
    __half2 h = __halves2half2(a, b);
    return *(uint32_t*)&h;
}
__device__ __forceinline__ void mma_f16(float* d, const uint32_t* a, const uint32_t* b) {
    asm volatile(
        "mma.sync.aligned.m16n8k16.row.col.f32.f16.f16.f32 "
        "{%0,%1,%2,%3}, {%4,%5,%6,%7}, {%8,%9}, {%0,%1,%2,%3};"
        : "+f"(d[0]), "+f"(d[1]), "+f"(d[2]), "+f"(d[3])
        : "r"(a[0]), "r"(a[1]), "r"(a[2]), "r"(a[3]), "r"(b[0]), "r"(b[1]));
}
__device__ __forceinline__ void ldsm4(uint32_t* r, uint32_t a) {
    asm volatile("ldmatrix.sync.aligned.m8n8.x4.shared.b16 {%0,%1,%2,%3}, [%4];"
        : "=r"(r[0]), "=r"(r[1]), "=r"(r[2]), "=r"(r[3]) : "r"(a));
}
__device__ __forceinline__ void ldsm2(uint32_t* r, uint32_t a) {
    asm volatile("ldmatrix.sync.aligned.m8n8.x2.shared.b16 {%0,%1}, [%2];"
        : "=r"(r[0]), "=r"(r[1]) : "r"(a));
}
// monotone float<->uint encoding for atomicMax over signed floats
__device__ __forceinline__ uint32_t fenc(float f) {
    uint32_t u = __float_as_uint(f);
    return (u & 0x80000000u) ? ~u : (u | 0x80000000u);
}
__device__ __forceinline__ float fdec(uint32_t e) {
    uint32_t u = (e & 0x80000000u) ? (e & 0x7fffffffu) : ~e;
    return __uint_as_float(u);
}

// ===========================================================================
// Kernel 0: W pre-transpose + fp16 hi/lo pre-split; init row-max table.
// ===========================================================================
__global__ void wtrans_kernel(const float* __restrict__ Wf,
                              const float* __restrict__ Wg,
                              const float* __restrict__ Wh) {
    int idx = blockIdx.x * 256 + threadIdx.x;       // 320*256 total
    if (idx < Bb * Nq) g_rowmaxE[idx] = 0u;         // < any real encoded value
    int n = idx >> 8, k = idx & 255;
    float w;
    if (n < 32)       w = Wf[k * CK + n];
    else if (n < 64)  w = Wg[k * CK + (n - 32)];
    else              w = Wh[k * C + (n - 64)];
    __half hi = __float2half_rn(w);
    g_WT[n * 256 + k] = hi;
    if (n < 64)
        g_WTlo[n * 256 + k] = __float2half_rn(w - __half2float(hi));
}

// ===========================================================================
// Kernel 1: fused projections, fp16 mma. CTA 64 rows x 320 cols, K=256.
// ===========================================================================
constexpr int XH_OFF = 0;          // 64*80   = 5120
constexpr int XL_OFF = 5120;       // 5120
constexpr int WH_OFF = 10240;      // 320*80  = 25600
constexpr int WL_OFF = 35840;      // 64*80   = 5120
constexpr int PJ_SMEM = 40960;

__global__ __launch_bounds__(256, 2)
void proj_kernel(const float* __restrict__ x,
                 const float* __restrict__ bfv, const float* __restrict__ bgv,
                 const float* __restrict__ bhv) {
    extern __shared__ char dsm[];
    const uint32_t base = smem_u32(dsm);

    const int t = threadIdx.x;
    const int lane = t & 31, wid = t >> 5;
    const int wm = wid >> 2, wn = wid & 3;
    const int rowbase = blockIdx.x * 64;

    const int arow   = (lane & 7) + ((lane >> 3) & 1) * 8;
    const int acol16 = (lane >> 4) * 16;
    const int brow2  = lane & 7;
    const int bcol16 = ((lane >> 3) & 1) * 16;

    float acc[2][10][4] = {};
    float4 va[2], vb[2];

    auto ldgX = [&](int ch, float4* v) {
        #pragma unroll
        for (int i = 0; i < 2; i++) {
            int idx = t + i * 256;
            int r = idx >> 3, c4 = (idx & 7) * 4;
            v[i] = *(const float4*)(x + (size_t)(rowbase + r) * C + ch * 32 + c4);
        }
    };
    auto stsX = [&](const float4* v) {
        #pragma unroll
        for (int i = 0; i < 2; i++) {
            int idx = t + i * 256;
            int r = idx >> 3, c4 = (idx & 7) * 4;
            float f[4] = {v[i].x, v[i].y, v[i].z, v[i].w};
            __half h[4], l[4];
            #pragma unroll
            for (int e = 0; e < 4; e++) {
                h[e] = __float2half_rn(f[e]);
                l[e] = __float2half_rn(f[e] - __half2float(h[e]));
            }
            uint2 uh, ul;
            uh.x = pack2(h[0], h[1]); uh.y = pack2(h[2], h[3]);
            ul.x = pack2(l[0], l[1]); ul.y = pack2(l[2], l[3]);
            *(uint2*)(dsm + XH_OFF + r * 80 + c4 * 2) = uh;
            *(uint2*)(dsm + XL_OFF + r * 80 + c4 * 2) = ul;
        }
    };

    ldgX(0, va);
    for (int ch = 0; ch < 8; ch++) {
        __syncthreads();            // prev chunk's mma reads done
        stsX(va);
        if (ch < 7) ldgX(ch + 1, vb);
        #pragma unroll
        for (int i = 0; i < 5; i++) {          // W hi: 1280 cp16
            int idx = t + i * 256;
            int r = idx >> 2, seg = idx & 3;
            cp16(base + WH_OFF + r * 80 + seg * 16, g_WT + r * 256 + ch * 32 + seg * 8);
        }
        {
            int r = t >> 2, seg = t & 3;       // W lo: 256 cp16
            cp16(base + WL_OFF + r * 80 + seg * 16, g_WTlo + r * 256 + ch * 32 + seg * 8);
        }
        cp_commit();
        asm volatile("cp.async.wait_group 0;" ::: "memory");
        __syncthreads();

        #pragma unroll
        for (int ks = 0; ks < 2; ks++) {
            uint32_t ah[2][4], al[2][4];
            #pragma unroll
            for (int mt = 0; mt < 2; mt++) {
                uint32_t off = (wm * 32 + mt * 16 + arow) * 80 + ks * 32 + acol16;
                ldsm4(ah[mt], base + XH_OFF + off);
                ldsm4(al[mt], base + XL_OFF + off);
            }
            #pragma unroll
            for (int nt = 0; nt < 10; nt++) {
                const int c0 = nt * 32 + wn * 8;
                uint32_t off = (c0 + brow2) * 80 + ks * 32 + bcol16;
                uint32_t bh[2];
                ldsm2(bh, base + WH_OFF + off);
                if (nt < 2) {
                    uint32_t bl[2];
                    ldsm2(bl, base + WL_OFF + off);
                    #pragma unroll
                    for (int mt = 0; mt < 2; mt++) {
                        mma_f16(acc[mt][nt], ah[mt], bh);
                        mma_f16(acc[mt][nt], ah[mt], bl);
                        mma_f16(acc[mt][nt], al[mt], bh);
                    }
                } else {
                    #pragma unroll
                    for (int mt = 0; mt < 2; mt++)
                        mma_f16(acc[mt][nt], ah[mt], bh);
                }
            }
        }
        va[0] = vb[0]; va[1] = vb[1];
    }

    // epilogue
    #pragma unroll
    for (int nt = 0; nt < 10; nt++) {
        const int c0 = nt * 32 + wn * 8 + 2 * (lane & 3);
        #pragma unroll
        for (int mt = 0; mt < 2; mt++) {
            const int r0 = rowbase + wm * 32 + mt * 16 + (lane >> 2);
            #pragma unroll
            for (int h2 = 0; h2 < 2; h2++) {
                const int r = r0 + h2 * 8;
                const float d0 = acc[mt][nt][h2 * 2 + 0];
                const float d1 = acc[mt][nt][h2 * 2 + 1];
                if (nt == 0) {
                    float v0 = d0 + bfv[c0], v1 = d1 + bfv[c0 + 1];
                    __half a0 = __float2half_rn(v0), a1 = __float2half_rn(v1);
                    __half b0 = __float2half_rn(v0 - __half2float(a0));
                    __half b1 = __float2half_rn(v1 - __half2float(a1));
                    *(uint32_t*)(g_f  + (size_t)r * CK + c0) = pack2(a0, a1);
                    *(uint32_t*)(g_fl + (size_t)r * CK + c0) = pack2(b0, b1);
                } else if (nt == 1) {
                    int c = c0 - 32;
                    float v0 = d0 + bgv[c], v1 = d1 + bgv[c + 1];
                    __half a0 = __float2half_rn(v0), a1 = __float2half_rn(v1);
                    __half b0 = __float2half_rn(v0 - __half2float(a0));
                    __half b1 = __float2half_rn(v1 - __half2float(a1));
                    *(uint32_t*)(g_g  + (size_t)r * CK + c) = pack2(a0, a1);
                    *(uint32_t*)(g_gl + (size_t)r * CK + c) = pack2(b0, b1);
                } else {
                    int c = c0 - 64;
                    int bb = r >> 12, n = r & 4095;
                    g_hT[((size_t)bb * C + c) * Nq + n]     = __float2half_rn(d0 + bhv[c]);
                    g_hT[((size_t)bb * C + c + 1) * Nq + n] = __float2half_rn(d1 + bhv[c + 1]);
                }
            }
        }
    }
}

// ===========================================================================
// Kernel 2: scores via fp16 3-term hi/lo (fp32-grade) + per-row max.
// ===========================================================================
constexpr int GH_OFF = 0, GL_OFF = 10240, FH_OFF = 20480, FL_OFF = 30720;
constexpr int SC_SMEM = 40960;

__global__ __launch_bounds__(256)
void score_kernel() {
    extern __shared__ char dsm[];
    const uint32_t base = smem_u32(dsm);

    const int t = threadIdx.x;
    const int lane = t & 31, wid = t >> 5;
    const int wm = wid >> 2, wn = wid & 3;
    const int mbase = blockIdx.y * 128, nbase = blockIdx.x * 128;
    const int bz = blockIdx.z;
    const size_t zoff = (size_t)bz * Nq * CK;

    #pragma unroll
    for (int i = 0; i < 2; i++) {
        int idx = t + i * 256;
        int r = idx >> 2, seg = idx & 3;
        uint32_t so = r * 80 + seg * 16;
        cp16(base + GH_OFF + so, g_g  + zoff + (size_t)(mbase + r) * CK + seg * 8);
        cp16(base + GL_OFF + so, g_gl + zoff + (size_t)(mbase + r) * CK + seg * 8);
        cp16(base + FH_OFF + so, g_f  + zoff + (size_t)(nbase + r) * CK + seg * 8);
        cp16(base + FL_OFF + so, g_fl + zoff + (size_t)(nbase + r) * CK + seg * 8);
    }
    cp_commit();
    asm volatile("cp.async.wait_group 0;" ::: "memory");
    __syncthreads();

    const int arow   = (lane & 7) + ((lane >> 3) & 1) * 8;
    const int acol16 = (lane >> 4) * 16;
    const int brow   = (lane >> 4) * 8 + (lane & 7);
    const int bcol16 = ((lane >> 3) & 1) * 16;

    float acc[4][4][4] = {};
    #pragma unroll
    for (int ks = 0; ks < 2; ks++) {
        uint32_t ah[4][4], al[4][4];
        #pragma unroll
        for (int mt = 0; mt < 4; mt++) {
            uint32_t off = (wm * 64 + mt * 16 + arow) * 80 + ks * 32 + acol16;
            ldsm4(ah[mt], base + GH_OFF + off);
            ldsm4(al[mt], base + GL_OFF + off);
        }
        #pragma unroll
        for (int j = 0; j < 2; j++) {
            uint32_t bh[4], bl[4];
            uint32_t off = (wn * 32 + j * 16 + brow) * 80 + ks * 32 + bcol16;
            ldsm4(bh, base + FH_OFF + off);
            ldsm4(bl, base + FL_OFF + off);
            #pragma unroll
            for (int sub = 0; sub < 2; sub++) {
                #pragma unroll
                for (int mt = 0; mt < 4; mt++) {
                    mma_f16(acc[mt][2 * j + sub], ah[mt], bh + sub * 2);
                    mma_f16(acc[mt][2 * j + sub], ah[mt], bl + sub * 2);
                    mma_f16(acc[mt][2 * j + sub], al[mt], bh + sub * 2);
                }
            }
        }
    }

    float* sout = g_s + (size_t)bz * Nq * Nq;
    #pragma unroll
    for (int mt = 0; mt < 4; mt++) {
        int r0 = mbase + wm * 64 + mt * 16 + (lane >> 2);
        float mx0 = -3.4e38f, mx1 = -3.4e38f;
        #pragma unroll
        for (int nt = 0; nt < 4; nt++) {
            int col = nbase + wn * 32 + nt * 8 + 2 * (lane & 3);
            float2 o0; o0.x = acc[mt][nt][0]; o0.y = acc[mt][nt][1];
            *(float2*)(sout + (size_t)r0 * Nq + col) = o0;
            float2 o1; o1.x = acc[mt][nt][2]; o1.y = acc[mt][nt][3];
            *(float2*)(sout + (size_t)(r0 + 8) * Nq + col) = o1;
            mx0 = fmaxf(mx0, fmaxf(o0.x, o0.y));
            mx1 = fmaxf(mx1, fmaxf(o1.x, o1.y));
        }
        mx0 = fmaxf(mx0, __shfl_xor_sync(0xffffffffu, mx0, 1));
        mx0 = fmaxf(mx0, __shfl_xor_sync(0xffffffffu, mx0, 2));
        mx1 = fmaxf(mx1, __shfl_xor_sync(0xffffffffu, mx1, 1));
        mx1 = fmaxf(mx1, __shfl_xor_sync(0xffffffffu, mx1, 2));
        if ((lane & 3) == 0) {
            atomicMax(&g_rowmaxE[bz * Nq + r0],     fenc(mx0));
            atomicMax(&g_rowmaxE[bz * Nq + r0 + 8], fenc(mx1));
        }
    }
}

// ===========================================================================
// Kernel 3: fused softmax + PV (fp16 mma) + residual.
//   512 threads, 16 warps (2m x 8n), warp tile 64x32 -> acc 64 regs,
//   4 warps/SMSP to hide exp/LDG/barrier under the HMMA stream.
//   A 3-stage exp pipeline, B 4-stage cp.async. Pitch 80B.
// ===========================================================================
constexpr int PV_A_OFF = 0;          // 3 * 128*80 = 30720
constexpr int PV_B_OFF = 30720;      // 4 * 256*80 = 81920
constexpr int PV_Z_OFF = 112640;     // 128 f32
constexpr int PV_SMEM  = 113152;
constexpr int NCH = Nq / 32;         // 128

__global__ __launch_bounds__(512, 1)
void pv_kernel(const float* __restrict__ gamma_p,
               const float* __restrict__ x, float* __restrict__ y) {
    extern __shared__ char dsm[];
    const uint32_t base = smem_u32(dsm);
    float* zsm = (float*)(dsm + PV_Z_OFF);

    const int t = threadIdx.x;
    const int lane = t & 31, wid = t >> 5;
    const int wm = wid >> 3, wn = wid & 7;         // 2(M) x 8(N)
    const int qbase = blockIdx.x * 128;
    const int b = blockIdx.y;
    const float*  Pm  = g_s  + (size_t)b * Nq * Nq;
    const __half* hTb = g_hT + (size_t)b * C * Nq;

    if (t < 128) zsm[t] = 0.f;

    const int tr  = t >> 3;          // 0..63
    const int tc4 = (t & 7) * 4;

    const int arow   = (lane & 7) + ((lane >> 3) & 1) * 8;
    const int acol16 = (lane >> 4) * 16;
    const int brow   = (lane >> 4) * 8 + (lane & 7);
    const int bcol16 = ((lane >> 3) & 1) * 16;

    float rm[2];
    rm[0] = fdec(g_rowmaxE[b * Nq + qbase + tr]);
    rm[1] = fdec(g_rowmaxE[b * Nq + qbase + tr + 64]);

    float4 va[2], vb[2];
    float zp[2] = {0.f, 0.f};

    auto ldgA = [&](int chunk, float4* v) {
        const float* bp = Pm + (size_t)(qbase + tr) * Nq + chunk * 32 + tc4;
        v[0] = *(const float4*)(bp);
        v[1] = *(const float4*)(bp + (size_t)64 * Nq);
    };
    auto expSts = [&](int chunk, const float4* v) {
        char* Ad = dsm + PV_A_OFF + (chunk % 3) * 10240;
        #pragma unroll
        for (int i = 0; i < 2; i++) {
            float p0 = __expf(v[i].x - rm[i]);
            float p1 = __expf(v[i].y - rm[i]);
            float p2 = __expf(v[i].z - rm[i]);
            float p3 = __expf(v[i].w - rm[i]);
            zp[i] += (p0 + p1) + (p2 + p3);
            uint2 u;
            u.x = pack2(__float2half_rn(p0), __float2half_rn(p1));
            u.y = pack2(__float2half_rn(p2), __float2half_rn(p3));
            *(uint2*)(Ad + (tr + 64 * i) * 80 + tc4 * 2) = u;
        }
    };
    auto cpB = [&](int chunk) {
        uint32_t Bd = base + PV_B_OFF + (chunk & 3) * 20480;
        #pragma unroll
        for (int i = 0; i < 2; i++) {
            int idx = t + i * 512;
            int r = idx >> 2, seg = idx & 3;
            cp16(Bd + r * 80 + seg * 16, hTb + (size_t)r * Nq + chunk * 32 + seg * 8);
        }
        cp_commit();
    };

    cpB(0); cpB(1); cpB(2);
    ldgA(0, va);
    expSts(0, va);
    ldgA(1, va);

    float acc[4][4][4] = {};   // warp tile 64(M) x 32(N)

    for (int c = 0; c < NCH; c++) {
        if (c + 1 < NCH) expSts(c + 1, va);
        if (c + 2 < NCH) ldgA(c + 2, vb);

        int pend = NCH - 1 - c;
        if (pend >= 2)      asm volatile("cp.async.wait_group 2;" ::: "memory");
        else if (pend == 1) asm volatile("cp.async.wait_group 1;" ::: "memory");
        else                asm volatile("cp.async.wait_group 0;" ::: "memory");
        __syncthreads();

        if (c + 3 < NCH) cpB(c + 3);

        const uint32_t AsbU = base + PV_A_OFF + (c % 3) * 10240;
        const uint32_t BsbU = base + PV_B_OFF + (c & 3) * 20480;
        #pragma unroll
        for (int ks = 0; ks < 2; ks++) {
            uint32_t af[4][4];
            #pragma unroll
            for (int mt = 0; mt < 4; mt++)
                ldsm4(af[mt], AsbU + (wm * 64 + mt * 16 + arow) * 80 + ks * 32 + acol16);
            #pragma unroll
            for (int j = 0; j < 2; j++) {
                uint32_t bf[4];
                ldsm4(bf, BsbU + (wn * 32 + j * 16 + brow) * 80 + ks * 32 + bcol16);
                #pragma unroll
                for (int mt = 0; mt < 4; mt++) {
                    mma_f16(acc[mt][2 * j + 0], af[mt], bf + 0);
                    mma_f16(acc[mt][2 * j + 1], af[mt], bf + 2);
                }
            }
        }

        va[0] = vb[0]; va[1] = vb[1];
    }

    __syncthreads();
    atomicAdd(&zsm[tr], zp[0]);
    atomicAdd(&zsm[tr + 64], zp[1]);
    __syncthreads();

    const float gam = __ldg(gamma_p);
    #pragma unroll
    for (int mt = 0; mt < 4; mt++) {
        int row0 = wm * 64 + mt * 16 + (lane >> 2);
        float sc0 = gam / zsm[row0];
        float sc1 = gam / zsm[row0 + 8];
        #pragma unroll
        for (int nt = 0; nt < 4; nt++) {
            int col = wn * 32 + nt * 8 + 2 * (lane & 3);
            size_t bo = ((size_t)b * Nq + qbase + row0) * C + col;
            float2 x0 = *(const float2*)(x + bo);
            float2 o0;
            o0.x = sc0 * acc[mt][nt][0] + x0.x;
            o0.y = sc0 * acc[mt][nt][1] + x0.y;
            *(float2*)(y + bo) = o0;
            size_t bo2 = bo + 8 * (size_t)C;
            float2 x1 = *(const float2*)(x + bo2);
            float2 o1;
            o1.x = sc1 * acc[mt][nt][2] + x1.x;
            o1.y = sc1 * acc[mt][nt][3] + x1.y;
            *(float2*)(y + bo2) = o1;
        }
    }
}

// ===========================================================================
extern "C" void kernel_launch(void* const* d_in, const int* in_sizes, int n_in,
                              void* d_out, int out_size) {
    (void)in_sizes; (void)n_in; (void)out_size;
    const float* x     = (const float*)d_in[0];
    const float* Wf    = (const float*)d_in[1];
    const float* bf    = (const float*)d_in[2];
    const float* Wg    = (const float*)d_in[3];
    const float* bg    = (const float*)d_in[4];
    const float* Wh    = (const float*)d_in[5];
    const float* bh    = (const float*)d_in[6];
    const float* gamma = (const float*)d_in[7];
    float* y = (float*)d_out;

    cudaFuncSetAttribute(proj_kernel, cudaFuncAttributeMaxDynamicSharedMemorySize, PJ_SMEM);
    cudaFuncSetAttribute(score_kernel, cudaFuncAttributeMaxDynamicSharedMemorySize, SC_SMEM);
    cudaFuncSetAttribute(pv_kernel, cudaFuncAttributeMaxDynamicSharedMemorySize, PV_SMEM);

    wtrans_kernel<<<320, 256>>>(Wf, Wg, Wh);
    proj_kernel<<<(Bb * Nq) / 64, 256, PJ_SMEM>>>(x, bf, bg, bh);
    score_kernel<<<dim3(Nq / 128, Nq / 128, Bb), 256, SC_SMEM>>>();
    pv_kernel<<<dim3(Nq / 128, Bb), 512, PV_SMEM>>>(gamma, x, y);
}

// round 13
// speedup vs baseline: 1.5391x; 1.0134x over previous
#include <cuda_runtime.h>
#include <cuda_fp16.h>
#include <cstdint>

// Problem dims (fixed by dataset)
constexpr int Bb = 4;      // batch
constexpr int Nq = 4096;   // H*W
constexpr int C  = 256;    // channels
constexpr int CK = 32;     // key/query channels

// Scratch in __device__ globals (allocation-free rule)
__device__ __half g_f [(size_t)Bb * Nq * CK];            // keys   (fp16 hi)
__device__ __half g_fl[(size_t)Bb * Nq * CK];            // keys   (fp16 lo residual)
__device__ __half g_g [(size_t)Bb * Nq * CK];            // queries(fp16 hi)
__device__ __half g_gl[(size_t)Bb * Nq * CK];            // queries(fp16 lo residual)
__device__ __half g_hT[(size_t)Bb * C * Nq];             // values, transposed, fp16
__device__ float  g_s [(size_t)Bb * Nq * Nq];            // raw scores fp32 (256 MB)
__device__ __half g_WT  [320 * 256];                     // [Wf|Wg|Wh]^T fp16 hi
__device__ __half g_WTlo[64 * 256];                      // lo residual for f,g cols
__device__ unsigned int g_rowmaxE[Bb * Nq];              // encoded row maxes

__device__ __forceinline__ uint32_t smem_u32(const void* p) {
    return (uint32_t)__cvta_generic_to_shared(p);
}
__device__ __forceinline__ void cp16(uint32_t s, const void* g) {
    asm volatile("cp.async.cg.shared.global [%0], [%1], 16;" :: "r"(s), "l"(g));
}
__device__ __forceinline__ void cp_commit() {
    asm volatile("cp.async.commit_group;" ::: "memory");
}
__device__ __forceinline__ uint32_t pack2(__half a, __half b) {
    __half2 h = __halves2half2(a, b);
    return *(uint32_t*)&h;
}
__device__ __forceinline__ void mma_f16(float* d, const uint32_t* a, const uint32_t* b) {
    asm volatile(
        "mma.sync.aligned.m16n8k16.row.col.f32.f16.f16.f32 "
        "{%0,%1,%2,%3}, {%4,%5,%6,%7}, {%8,%9}, {%0,%1,%2,%3};"
        : "+f"(d[0]), "+f"(d[1]), "+f"(d[2]), "+f"(d[3])
        : "r"(a[0]), "r"(a[1]), "r"(a[2]), "r"(a[3]), "r"(b[0]), "r"(b[1]));
}
__device__ __forceinline__ void ldsm4(uint32_t* r, uint32_t a) {
    asm volatile("ldmatrix.sync.aligned.m8n8.x4.shared.b16 {%0,%1,%2,%3}, [%4];"
        : "=r"(r[0]), "=r"(r[1]), "=r"(r[2]), "=r"(r[3]) : "r"(a));
}
__device__ __forceinline__ void ldsm2(uint32_t* r, uint32_t a) {
    asm volatile("ldmatrix.sync.aligned.m8n8.x2.shared.b16 {%0,%1}, [%2];"
        : "=r"(r[0]), "=r"(r[1]) : "r"(a));
}
// monotone float<->uint encoding for atomicMax over signed floats
__device__ __forceinline__ uint32_t fenc(float f) {
    uint32_t u = __float_as_uint(f);
    return (u & 0x80000000u) ? ~u : (u | 0x80000000u);
}
__device__ __forceinline__ float fdec(uint32_t e) {
    uint32_t u = (e & 0x80000000u) ? (e & 0x7fffffffu) : ~e;
    return __uint_as_float(u);
}

// ===========================================================================
// Kernel 0: W pre-transpose + fp16 hi/lo pre-split; init row-max table.
// ===========================================================================
__global__ void wtrans_kernel(const float* __restrict__ Wf,
                              const float* __restrict__ Wg,
                              const float* __restrict__ Wh) {
    int idx = blockIdx.x * 256 + threadIdx.x;       // 320*256 total
    if (idx < Bb * Nq) g_rowmaxE[idx] = 0u;         // < any real encoded value
    int n = idx >> 8, k = idx & 255;
    float w;
    if (n < 32)       w = Wf[k * CK + n];
    else if (n < 64)  w = Wg[k * CK + (n - 32)];
    else              w = Wh[k * C + (n - 64)];
    __half hi = __float2half_rn(w);
    g_WT[n * 256 + k] = hi;
    if (n < 64)
        g_WTlo[n * 256 + k] = __float2half_rn(w - __half2float(hi));
}

// ===========================================================================
// Kernel 1: fused projections, fp16 mma. CTA 64 rows x 320 cols, K=256. (R12)
// ===========================================================================
constexpr int XH_OFF = 0;          // 64*80   = 5120
constexpr int XL_OFF = 5120;       // 5120
constexpr int WH_OFF = 10240;      // 320*80  = 25600
constexpr int WL_OFF = 35840;      // 64*80   = 5120
constexpr int PJ_SMEM = 40960;

__global__ __launch_bounds__(256, 2)
void proj_kernel(const float* __restrict__ x,
                 const float* __restrict__ bfv, const float* __restrict__ bgv,
                 const float* __restrict__ bhv) {
    extern __shared__ char dsm[];
    const uint32_t base = smem_u32(dsm);

    const int t = threadIdx.x;
    const int lane = t & 31, wid = t >> 5;
    const int wm = wid >> 2, wn = wid & 3;
    const int rowbase = blockIdx.x * 64;

    const int arow   = (lane & 7) + ((lane >> 3) & 1) * 8;
    const int acol16 = (lane >> 4) * 16;
    const int brow2  = lane & 7;
    const int bcol16 = ((lane >> 3) & 1) * 16;

    float acc[2][10][4] = {};
    float4 va[2], vb[2];

    auto ldgX = [&](int ch, float4* v) {
        #pragma unroll
        for (int i = 0; i < 2; i++) {
            int idx = t + i * 256;
            int r = idx >> 3, c4 = (idx & 7) * 4;
            v[i] = *(const float4*)(x + (size_t)(rowbase + r) * C + ch * 32 + c4);
        }
    };
    auto stsX = [&](const float4* v) {
        #pragma unroll
        for (int i = 0; i < 2; i++) {
            int idx = t + i * 256;
            int r = idx >> 3, c4 = (idx & 7) * 4;
            float f[4] = {v[i].x, v[i].y, v[i].z, v[i].w};
            __half h[4], l[4];
            #pragma unroll
            for (int e = 0; e < 4; e++) {
                h[e] = __float2half_rn(f[e]);
                l[e] = __float2half_rn(f[e] - __half2float(h[e]));
            }
            uint2 uh, ul;
            uh.x = pack2(h[0], h[1]); uh.y = pack2(h[2], h[3]);
            ul.x = pack2(l[0], l[1]); ul.y = pack2(l[2], l[3]);
            *(uint2*)(dsm + XH_OFF + r * 80 + c4 * 2) = uh;
            *(uint2*)(dsm + XL_OFF + r * 80 + c4 * 2) = ul;
        }
    };

    ldgX(0, va);
    for (int ch = 0; ch < 8; ch++) {
        __syncthreads();            // prev chunk's mma reads done
        stsX(va);
        if (ch < 7) ldgX(ch + 1, vb);
        #pragma unroll
        for (int i = 0; i < 5; i++) {          // W hi: 1280 cp16
            int idx = t + i * 256;
            int r = idx >> 2, seg = idx & 3;
            cp16(base + WH_OFF + r * 80 + seg * 16, g_WT + r * 256 + ch * 32 + seg * 8);
        }
        {
            int r = t >> 2, seg = t & 3;       // W lo: 256 cp16
            cp16(base + WL_OFF + r * 80 + seg * 16, g_WTlo + r * 256 + ch * 32 + seg * 8);
        }
        cp_commit();
        asm volatile("cp.async.wait_group 0;" ::: "memory");
        __syncthreads();

        #pragma unroll
        for (int ks = 0; ks < 2; ks++) {
            uint32_t ah[2][4], al[2][4];
            #pragma unroll
            for (int mt = 0; mt < 2; mt++) {
                uint32_t off = (wm * 32 + mt * 16 + arow) * 80 + ks * 32 + acol16;
                ldsm4(ah[mt], base + XH_OFF + off);
                ldsm4(al[mt], base + XL_OFF + off);
            }
            #pragma unroll
            for (int nt = 0; nt < 10; nt++) {
                const int c0 = nt * 32 + wn * 8;
                uint32_t off = (c0 + brow2) * 80 + ks * 32 + bcol16;
                uint32_t bh[2];
                ldsm2(bh, base + WH_OFF + off);
                if (nt < 2) {
                    uint32_t bl[2];
                    ldsm2(bl, base + WL_OFF + off);
                    #pragma unroll
                    for (int mt = 0; mt < 2; mt++) {
                        mma_f16(acc[mt][nt], ah[mt], bh);
                        mma_f16(acc[mt][nt], ah[mt], bl);
                        mma_f16(acc[mt][nt], al[mt], bh);
                    }
                } else {
                    #pragma unroll
                    for (int mt = 0; mt < 2; mt++)
                        mma_f16(acc[mt][nt], ah[mt], bh);
                }
            }
        }
        va[0] = vb[0]; va[1] = vb[1];
    }

    // epilogue
    #pragma unroll
    for (int nt = 0; nt < 10; nt++) {
        const int c0 = nt * 32 + wn * 8 + 2 * (lane & 3);
        #pragma unroll
        for (int mt = 0; mt < 2; mt++) {
            const int r0 = rowbase + wm * 32 + mt * 16 + (lane >> 2);
            #pragma unroll
            for (int h2 = 0; h2 < 2; h2++) {
                const int r = r0 + h2 * 8;
                const float d0 = acc[mt][nt][h2 * 2 + 0];
                const float d1 = acc[mt][nt][h2 * 2 + 1];
                if (nt == 0) {
                    float v0 = d0 + bfv[c0], v1 = d1 + bfv[c0 + 1];
                    __half a0 = __float2half_rn(v0), a1 = __float2half_rn(v1);
                    __half b0 = __float2half_rn(v0 - __half2float(a0));
                    __half b1 = __float2half_rn(v1 - __half2float(a1));
                    *(uint32_t*)(g_f  + (size_t)r * CK + c0) = pack2(a0, a1);
                    *(uint32_t*)(g_fl + (size_t)r * CK + c0) = pack2(b0, b1);
                } else if (nt == 1) {
                    int c = c0 - 32;
                    float v0 = d0 + bgv[c], v1 = d1 + bgv[c + 1];
                    __half a0 = __float2half_rn(v0), a1 = __float2half_rn(v1);
                    __half b0 = __float2half_rn(v0 - __half2float(a0));
                    __half b1 = __float2half_rn(v1 - __half2float(a1));
                    *(uint32_t*)(g_g  + (size_t)r * CK + c) = pack2(a0, a1);
                    *(uint32_t*)(g_gl + (size_t)r * CK + c) = pack2(b0, b1);
                } else {
                    int c = c0 - 64;
                    int bb = r >> 12, n = r & 4095;
                    g_hT[((size_t)bb * C + c) * Nq + n]     = __float2half_rn(d0 + bhv[c]);
                    g_hT[((size_t)bb * C + c + 1) * Nq + n] = __float2half_rn(d1 + bhv[c + 1]);
                }
            }
        }
    }
}

// ===========================================================================
// Kernel 2: scores via fp16 3-term hi/lo (fp32-grade) + per-row max. (R12)
// ===========================================================================
constexpr int GH_OFF = 0, GL_OFF = 10240, FH_OFF = 20480, FL_OFF = 30720;
constexpr int SC_SMEM = 40960;

__global__ __launch_bounds__(256)
void score_kernel() {
    extern __shared__ char dsm[];
    const uint32_t base = smem_u32(dsm);

    const int t = threadIdx.x;
    const int lane = t & 31, wid = t >> 5;
    const int wm = wid >> 2, wn = wid & 3;
    const int mbase = blockIdx.y * 128, nbase = blockIdx.x * 128;
    const int bz = blockIdx.z;
    const size_t zoff = (size_t)bz * Nq * CK;

    #pragma unroll
    for (int i = 0; i < 2; i++) {
        int idx = t + i * 256;
        int r = idx >> 2, seg = idx & 3;
        uint32_t so = r * 80 + seg * 16;
        cp16(base + GH_OFF + so, g_g  + zoff + (size_t)(mbase + r) * CK + seg * 8);
        cp16(base + GL_OFF + so, g_gl + zoff + (size_t)(mbase + r) * CK + seg * 8);
        cp16(base + FH_OFF + so, g_f  + zoff + (size_t)(nbase + r) * CK + seg * 8);
        cp16(base + FL_OFF + so, g_fl + zoff + (size_t)(nbase + r) * CK + seg * 8);
    }
    cp_commit();
    asm volatile("cp.async.wait_group 0;" ::: "memory");
    __syncthreads();

    const int arow   = (lane & 7) + ((lane >> 3) & 1) * 8;
    const int acol16 = (lane >> 4) * 16;
    const int brow   = (lane >> 4) * 8 + (lane & 7);
    const int bcol16 = ((lane >> 3) & 1) * 16;

    float acc[4][4][4] = {};
    #pragma unroll
    for (int ks = 0; ks < 2; ks++) {
        uint32_t ah[4][4], al[4][4];
        #pragma unroll
        for (int mt = 0; mt < 4; mt++) {
            uint32_t off = (wm * 64 + mt * 16 + arow) * 80 + ks * 32 + acol16;
            ldsm4(ah[mt], base + GH_OFF + off);
            ldsm4(al[mt], base + GL_OFF + off);
        }
        #pragma unroll
        for (int j = 0; j < 2; j++) {
            uint32_t bh[4], bl[4];
            uint32_t off = (wn * 32 + j * 16 + brow) * 80 + ks * 32 + bcol16;
            ldsm4(bh, base + FH_OFF + off);
            ldsm4(bl, base + FL_OFF + off);
            #pragma unroll
            for (int sub = 0; sub < 2; sub++) {
                #pragma unroll
                for (int mt = 0; mt < 4; mt++) {
                    mma_f16(acc[mt][2 * j + sub], ah[mt], bh + sub * 2);
                    mma_f16(acc[mt][2 * j + sub], ah[mt], bl + sub * 2);
                    mma_f16(acc[mt][2 * j + sub], al[mt], bh + sub * 2);
                }
            }
        }
    }

    float* sout = g_s + (size_t)bz * Nq * Nq;
    #pragma unroll
    for (int mt = 0; mt < 4; mt++) {
        int r0 = mbase + wm * 64 + mt * 16 + (lane >> 2);
        float mx0 = -3.4e38f, mx1 = -3.4e38f;
        #pragma unroll
        for (int nt = 0; nt < 4; nt++) {
            int col = nbase + wn * 32 + nt * 8 + 2 * (lane & 3);
            float2 o0; o0.x = acc[mt][nt][0]; o0.y = acc[mt][nt][1];
            *(float2*)(sout + (size_t)r0 * Nq + col) = o0;
            float2 o1; o1.x = acc[mt][nt][2]; o1.y = acc[mt][nt][3];
            *(float2*)(sout + (size_t)(r0 + 8) * Nq + col) = o1;
            mx0 = fmaxf(mx0, fmaxf(o0.x, o0.y));
            mx1 = fmaxf(mx1, fmaxf(o1.x, o1.y));
        }
        mx0 = fmaxf(mx0, __shfl_xor_sync(0xffffffffu, mx0, 1));
        mx0 = fmaxf(mx0, __shfl_xor_sync(0xffffffffu, mx0, 2));
        mx1 = fmaxf(mx1, __shfl_xor_sync(0xffffffffu, mx1, 1));
        mx1 = fmaxf(mx1, __shfl_xor_sync(0xffffffffu, mx1, 2));
        if ((lane & 3) == 0) {
            atomicMax(&g_rowmaxE[bz * Nq + r0],     fenc(mx0));
            atomicMax(&g_rowmaxE[bz * Nq + r0 + 8], fenc(mx1));
        }
    }
}

// ===========================================================================
// Kernel 3: fused softmax + PV (fp16 mma) + residual.  BK=64 chunks.
//   512 threads, 16 warps (2m x 8n), warp tile 64x32.
//   Pitch 144B (64 fp16 + pad). A 3 stages (exp path), B 3 stages (cp.async).
//   Half the barriers/waits of the BK=32 version.
// ===========================================================================
constexpr int PV_PITCH = 144;
constexpr int PV_A_ST  = 128 * PV_PITCH;            // 18432
constexpr int PV_B_ST  = 256 * PV_PITCH;            // 36864
constexpr int PV_A_OFF = 0;                         // 3 stages: 55296
constexpr int PV_B_OFF = 3 * PV_A_ST;               // 3 stages: 110592
constexpr int PV_Z_OFF = PV_B_OFF + 3 * PV_B_ST;    // 165888
constexpr int PV_SMEM  = PV_Z_OFF + 512;            // 166400
constexpr int NCH = Nq / 64;                        // 64

__global__ __launch_bounds__(512, 1)
void pv_kernel(const float* __restrict__ gamma_p,
               const float* __restrict__ x, float* __restrict__ y) {
    extern __shared__ char dsm[];
    const uint32_t base = smem_u32(dsm);
    float* zsm = (float*)(dsm + PV_Z_OFF);

    const int t = threadIdx.x;
    const int lane = t & 31, wid = t >> 5;
    const int wm = wid >> 3, wn = wid & 7;         // 2(M) x 8(N)
    const int qbase = blockIdx.x * 128;
    const int b = blockIdx.y;
    const float*  Pm  = g_s  + (size_t)b * Nq * Nq;
    const __half* hTb = g_hT + (size_t)b * C * Nq;

    if (t < 128) zsm[t] = 0.f;

    const int tr = t >> 2;           // 0..127: one q-row per thread
    const int cb = (t & 3) * 16;     // 16 contiguous cols per thread

    const int arow   = (lane & 7) + ((lane >> 3) & 1) * 8;
    const int acol16 = (lane >> 4) * 16;
    const int brow   = (lane >> 4) * 8 + (lane & 7);
    const int bcol16 = ((lane >> 3) & 1) * 16;

    const float rm = fdec(g_rowmaxE[b * Nq + qbase + tr]);

    float4 va[4];
    float zp = 0.f;

    auto ldgA = [&](int chunk) {
        const float* bp = Pm + (size_t)(qbase + tr) * Nq + chunk * 64 + cb;
        #pragma unroll
        for (int i = 0; i < 4; i++)
            va[i] = *(const float4*)(bp + i * 4);
    };
    auto expSts = [&](int chunk) {
        char* Ad = dsm + PV_A_OFF + (chunk % 3) * PV_A_ST;
        #pragma unroll
        for (int i = 0; i < 4; i++) {
            float p0 = __expf(va[i].x - rm);
            float p1 = __expf(va[i].y - rm);
            float p2 = __expf(va[i].z - rm);
            float p3 = __expf(va[i].w - rm);
            zp += (p0 + p1) + (p2 + p3);
            uint2 u;
            u.x = pack2(__float2half_rn(p0), __float2half_rn(p1));
            u.y = pack2(__float2half_rn(p2), __float2half_rn(p3));
            *(uint2*)(Ad + tr * PV_PITCH + (cb + i * 4) * 2) = u;
        }
    };
    auto cpB = [&](int chunk) {
        uint32_t Bd = base + PV_B_OFF + (chunk % 3) * PV_B_ST;
        #pragma unroll
        for (int i = 0; i < 4; i++) {
            int idx = t + i * 512;
            int r = idx >> 3, seg = idx & 7;
            cp16(Bd + r * PV_PITCH + seg * 16, hTb + (size_t)r * Nq + chunk * 64 + seg * 8);
        }
        cp_commit();
    };

    // prologue
    cpB(0); cpB(1);
    ldgA(0);
    expSts(0);
    ldgA(1);

    float acc[4][4][4] = {};   // warp tile 64(M) x 32(N)

    for (int c = 0; c < NCH; c++) {
        if (c + 1 < NCH) expSts(c + 1);     // consumes va (chunk c+1)
        if (c + 2 < NCH) ldgA(c + 2);       // refills va

        if (c + 1 < NCH) asm volatile("cp.async.wait_group 1;" ::: "memory");
        else             asm volatile("cp.async.wait_group 0;" ::: "memory");
        __syncthreads();

        if (c + 2 < NCH) cpB(c + 2);

        const uint32_t AsbU = base + PV_A_OFF + (c % 3) * PV_A_ST;
        const uint32_t BsbU = base + PV_B_OFF + (c % 3) * PV_B_ST;
        #pragma unroll
        for (int ks = 0; ks < 4; ks++) {
            uint32_t af[4][4];
            #pragma unroll
            for (int mt = 0; mt < 4; mt++)
                ldsm4(af[mt], AsbU + (wm * 64 + mt * 16 + arow) * PV_PITCH + ks * 32 + acol16);
            #pragma unroll
            for (int j = 0; j < 2; j++) {
                uint32_t bf[4];
                ldsm4(bf, BsbU + (wn * 32 + j * 16 + brow) * PV_PITCH + ks * 32 + bcol16);
                #pragma unroll
                for (int mt = 0; mt < 4; mt++) {
                    mma_f16(acc[mt][2 * j + 0], af[mt], bf + 0);
                    mma_f16(acc[mt][2 * j + 1], af[mt], bf + 2);
                }
            }
        }
    }

    __syncthreads();
    atomicAdd(&zsm[tr], zp);
    __syncthreads();

    const float gam = __ldg(gamma_p);
    #pragma unroll
    for (int mt = 0; mt < 4; mt++) {
        int row0 = wm * 64 + mt * 16 + (lane >> 2);
        float sc0 = gam / zsm[row0];
        float sc1 = gam / zsm[row0 + 8];
        #pragma unroll
        for (int nt = 0; nt < 4; nt++) {
            int col = wn * 32 + nt * 8 + 2 * (lane & 3);
            size_t bo = ((size_t)b * Nq + qbase + row0) * C + col;
            float2 x0 = *(const float2*)(x + bo);
            float2 o0;
            o0.x = sc0 * acc[mt][nt][0] + x0.x;
            o0.y = sc0 * acc[mt][nt][1] + x0.y;
            *(float2*)(y + bo) = o0;
            size_t bo2 = bo + 8 * (size_t)C;
            float2 x1 = *(const float2*)(x + bo2);
            float2 o1;
            o1.x = sc1 * acc[mt][nt][2] + x1.x;
            o1.y = sc1 * acc[mt][nt][3] + x1.y;
            *(float2*)(y + bo2) = o1;
        }
    }
}

// ===========================================================================
extern "C" void kernel_launch(void* const* d_in, const int* in_sizes, int n_in,
                              void* d_out, int out_size) {
    (void)in_sizes; (void)n_in; (void)out_size;
    const float* x     = (const float*)d_in[0];
    const float* Wf    = (const float*)d_in[1];
    const float* bf    = (const float*)d_in[2];
    const float* Wg    = (const float*)d_in[3];
    const float* bg    = (const float*)d_in[4];
    const float* Wh    = (const float*)d_in[5];
    const float* bh    = (const float*)d_in[6];
    const float* gamma = (const float*)d_in[7];
    float* y = (float*)d_out;

    cudaFuncSetAttribute(proj_kernel, cudaFuncAttributeMaxDynamicSharedMemorySize, PJ_SMEM);
    cudaFuncSetAttribute(score_kernel, cudaFuncAttributeMaxDynamicSharedMemorySize, SC_SMEM);
    cudaFuncSetAttribute(pv_kernel, cudaFuncAttributeMaxDynamicSharedMemorySize, PV_SMEM);

    wtrans_kernel<<<320, 256>>>(Wf, Wg, Wh);
    proj_kernel<<<(Bb * Nq) / 64, 256, PJ_SMEM>>>(x, bf, bg, bh);
    score_kernel<<<dim3(Nq / 128, Nq / 128, Bb), 256, SC_SMEM>>>();
    pv_kernel<<<dim3(Nq / 128, Bb), 512, PV_SMEM>>>(gamma, x, y);
}

// round 14
// speedup vs baseline: 1.6723x; 1.0866x over previous
#include <cuda_runtime.h>
#include <cuda_fp16.h>
#include <cstdint>

// Problem dims (fixed by dataset)
constexpr int Bb = 4;      // batch
constexpr int Nq = 4096;   // H*W
constexpr int C  = 256;    // channels
constexpr int CK = 32;     // key/query channels

// Scratch in __device__ globals (allocation-free rule)
__device__ __half g_f [(size_t)Bb * Nq * CK];            // keys   (fp16 hi)
__device__ __half g_fl[(size_t)Bb * Nq * CK];            // keys   (fp16 lo residual)
__device__ __half g_g [(size_t)Bb * Nq * CK];            // queries(fp16 hi)
__device__ __half g_gl[(size_t)Bb * Nq * CK];            // queries(fp16 lo residual)
__device__ __half g_hT[(size_t)Bb * C * Nq];             // values, transposed, fp16
__device__ float  g_s [(size_t)Bb * Nq * Nq];            // raw scores fp32 (256 MB)
__device__ __half g_WT  [320 * 256];                     // [Wf|Wg|Wh]^T fp16 hi
__device__ __half g_WTlo[64 * 256];                      // lo residual for f,g cols
__device__ unsigned int g_rowmaxE[Bb * Nq];              // encoded row maxes

__device__ __forceinline__ uint32_t smem_u32(const void* p) {
    return (uint32_t)__cvta_generic_to_shared(p);
}
__device__ __forceinline__ void cp16(uint32_t s, const void* g) {
    asm volatile("cp.async.cg.shared.global [%0], [%1], 16;" :: "r"(s), "l"(g));
}
__device__ __forceinline__ void cp_commit() {
    asm volatile("cp.async.commit_group;" ::: "memory");
}
__device__ __forceinline__ uint32_t pack2(__half a, __half b) {
    __half2 h = __halves2half2(a, b);
    return *(uint32_t*)&h;
}
__device__ __forceinline__ void mma_f16(float* d, const uint32_t* a, const uint32_t* b) {
    asm volatile(
        "mma.sync.aligned.m16n8k16.row.col.f32.f16.f16.f32 "
        "{%0,%1,%2,%3}, {%4,%5,%6,%7}, {%8,%9}, {%0,%1,%2,%3};"
        : "+f"(d[0]), "+f"(d[1]), "+f"(d[2]), "+f"(d[3])
        : "r"(a[0]), "r"(a[1]), "r"(a[2]), "r"(a[3]), "r"(b[0]), "r"(b[1]));
}
__device__ __forceinline__ void ldsm4(uint32_t* r, uint32_t a) {
    asm volatile("ldmatrix.sync.aligned.m8n8.x4.shared.b16 {%0,%1,%2,%3}, [%4];"
        : "=r"(r[0]), "=r"(r[1]), "=r"(r[2]), "=r"(r[3]) : "r"(a));
}
__device__ __forceinline__ void ldsm2(uint32_t* r, uint32_t a) {
    asm volatile("ldmatrix.sync.aligned.m8n8.x2.shared.b16 {%0,%1}, [%2];"
        : "=r"(r[0]), "=r"(r[1]) : "r"(a));
}
// monotone float<->uint encoding for atomicMax over signed floats
__device__ __forceinline__ uint32_t fenc(float f) {
    uint32_t u = __float_as_uint(f);
    return (u & 0x80000000u) ? ~u : (u | 0x80000000u);
}
__device__ __forceinline__ float fdec(uint32_t e) {
    uint32_t u = (e & 0x80000000u) ? (e & 0x7fffffffu) : ~e;
    return __uint_as_float(u);
}

// ===========================================================================
// Kernel 0: W pre-transpose + fp16 hi/lo pre-split; init row-max table.
// ===========================================================================
__global__ void wtrans_kernel(const float* __restrict__ Wf,
                              const float* __restrict__ Wg,
                              const float* __restrict__ Wh) {
    int idx = blockIdx.x * 256 + threadIdx.x;       // 320*256 total
    if (idx < Bb * Nq) g_rowmaxE[idx] = 0u;         // < any real encoded value
    int n = idx >> 8, k = idx & 255;
    float w;
    if (n < 32)       w = Wf[k * CK + n];
    else if (n < 64)  w = Wg[k * CK + (n - 32)];
    else              w = Wh[k * C + (n - 64)];
    __half hi = __float2half_rn(w);
    g_WT[n * 256 + k] = hi;
    if (n < 64)
        g_WTlo[n * 256 + k] = __float2half_rn(w - __half2float(hi));
}

// ===========================================================================
// Kernel 1: fused projections, fp16 mma. CTA 64 rows x 320 cols, K=256. (R12)
// ===========================================================================
constexpr int XH_OFF = 0;          // 64*80   = 5120
constexpr int XL_OFF = 5120;       // 5120
constexpr int WH_OFF = 10240;      // 320*80  = 25600
constexpr int WL_OFF = 35840;      // 64*80   = 5120
constexpr int PJ_SMEM = 40960;

__global__ __launch_bounds__(256, 2)
void proj_kernel(const float* __restrict__ x,
                 const float* __restrict__ bfv, const float* __restrict__ bgv,
                 const float* __restrict__ bhv) {
    extern __shared__ char dsm[];
    const uint32_t base = smem_u32(dsm);

    const int t = threadIdx.x;
    const int lane = t & 31, wid = t >> 5;
    const int wm = wid >> 2, wn = wid & 3;
    const int rowbase = blockIdx.x * 64;

    const int arow   = (lane & 7) + ((lane >> 3) & 1) * 8;
    const int acol16 = (lane >> 4) * 16;
    const int brow2  = lane & 7;
    const int bcol16 = ((lane >> 3) & 1) * 16;

    float acc[2][10][4] = {};
    float4 va[2], vb[2];

    auto ldgX = [&](int ch, float4* v) {
        #pragma unroll
        for (int i = 0; i < 2; i++) {
            int idx = t + i * 256;
            int r = idx >> 3, c4 = (idx & 7) * 4;
            v[i] = *(const float4*)(x + (size_t)(rowbase + r) * C + ch * 32 + c4);
        }
    };
    auto stsX = [&](const float4* v) {
        #pragma unroll
        for (int i = 0; i < 2; i++) {
            int idx = t + i * 256;
            int r = idx >> 3, c4 = (idx & 7) * 4;
            float f[4] = {v[i].x, v[i].y, v[i].z, v[i].w};
            __half h[4], l[4];
            #pragma unroll
            for (int e = 0; e < 4; e++) {
                h[e] = __float2half_rn(f[e]);
                l[e] = __float2half_rn(f[e] - __half2float(h[e]));
            }
            uint2 uh, ul;
            uh.x = pack2(h[0], h[1]); uh.y = pack2(h[2], h[3]);
            ul.x = pack2(l[0], l[1]); ul.y = pack2(l[2], l[3]);
            *(uint2*)(dsm + XH_OFF + r * 80 + c4 * 2) = uh;
            *(uint2*)(dsm + XL_OFF + r * 80 + c4 * 2) = ul;
        }
    };

    ldgX(0, va);
    for (int ch = 0; ch < 8; ch++) {
        __syncthreads();            // prev chunk's mma reads done
        stsX(va);
        if (ch < 7) ldgX(ch + 1, vb);
        #pragma unroll
        for (int i = 0; i < 5; i++) {          // W hi: 1280 cp16
            int idx = t + i * 256;
            int r = idx >> 2, seg = idx & 3;
            cp16(base + WH_OFF + r * 80 + seg * 16, g_WT + r * 256 + ch * 32 + seg * 8);
        }
        {
            int r = t >> 2, seg = t & 3;       // W lo: 256 cp16
            cp16(base + WL_OFF + r * 80 + seg * 16, g_WTlo + r * 256 + ch * 32 + seg * 8);
        }
        cp_commit();
        asm volatile("cp.async.wait_group 0;" ::: "memory");
        __syncthreads();

        #pragma unroll
        for (int ks = 0; ks < 2; ks++) {
            uint32_t ah[2][4], al[2][4];
            #pragma unroll
            for (int mt = 0; mt < 2; mt++) {
                uint32_t off = (wm * 32 + mt * 16 + arow) * 80 + ks * 32 + acol16;
                ldsm4(ah[mt], base + XH_OFF + off);
                ldsm4(al[mt], base + XL_OFF + off);
            }
            #pragma unroll
            for (int nt = 0; nt < 10; nt++) {
                const int c0 = nt * 32 + wn * 8;
                uint32_t off = (c0 + brow2) * 80 + ks * 32 + bcol16;
                uint32_t bh[2];
                ldsm2(bh, base + WH_OFF + off);
                if (nt < 2) {
                    uint32_t bl[2];
                    ldsm2(bl, base + WL_OFF + off);
                    #pragma unroll
                    for (int mt = 0; mt < 2; mt++) {
                        mma_f16(acc[mt][nt], ah[mt], bh);
                        mma_f16(acc[mt][nt], ah[mt], bl);
                        mma_f16(acc[mt][nt], al[mt], bh);
                    }
                } else {
                    #pragma unroll
                    for (int mt = 0; mt < 2; mt++)
                        mma_f16(acc[mt][nt], ah[mt], bh);
                }
            }
        }
        va[0] = vb[0]; va[1] = vb[1];
    }

    // epilogue
    #pragma unroll
    for (int nt = 0; nt < 10; nt++) {
        const int c0 = nt * 32 + wn * 8 + 2 * (lane & 3);
        #pragma unroll
        for (int mt = 0; mt < 2; mt++) {
            const int r0 = rowbase + wm * 32 + mt * 16 + (lane >> 2);
            #pragma unroll
            for (int h2 = 0; h2 < 2; h2++) {
                const int r = r0 + h2 * 8;
                const float d0 = acc[mt][nt][h2 * 2 + 0];
                const float d1 = acc[mt][nt][h2 * 2 + 1];
                if (nt == 0) {
                    float v0 = d0 + bfv[c0], v1 = d1 + bfv[c0 + 1];
                    __half a0 = __float2half_rn(v0), a1 = __float2half_rn(v1);
                    __half b0 = __float2half_rn(v0 - __half2float(a0));
                    __half b1 = __float2half_rn(v1 - __half2float(a1));
                    *(uint32_t*)(g_f  + (size_t)r * CK + c0) = pack2(a0, a1);
                    *(uint32_t*)(g_fl + (size_t)r * CK + c0) = pack2(b0, b1);
                } else if (nt == 1) {
                    int c = c0 - 32;
                    float v0 = d0 + bgv[c], v1 = d1 + bgv[c + 1];
                    __half a0 = __float2half_rn(v0), a1 = __float2half_rn(v1);
                    __half b0 = __float2half_rn(v0 - __half2float(a0));
                    __half b1 = __float2half_rn(v1 - __half2float(a1));
                    *(uint32_t*)(g_g  + (size_t)r * CK + c) = pack2(a0, a1);
                    *(uint32_t*)(g_gl + (size_t)r * CK + c) = pack2(b0, b1);
                } else {
                    int c = c0 - 64;
                    int bb = r >> 12, n = r & 4095;
                    g_hT[((size_t)bb * C + c) * Nq + n]     = __float2half_rn(d0 + bhv[c]);
                    g_hT[((size_t)bb * C + c + 1) * Nq + n] = __float2half_rn(d1 + bhv[c + 1]);
                }
            }
        }
    }
}

// ===========================================================================
// Kernel 2: scores via fp16 3-term hi/lo (fp32-grade) + per-row max. (R12)
// ===========================================================================
constexpr int GH_OFF = 0, GL_OFF = 10240, FH_OFF = 20480, FL_OFF = 30720;
constexpr int SC_SMEM = 40960;

__global__ __launch_bounds__(256)
void score_kernel() {
    extern __shared__ char dsm[];
    const uint32_t base = smem_u32(dsm);

    const int t = threadIdx.x;
    const int lane = t & 31, wid = t >> 5;
    const int wm = wid >> 2, wn = wid & 3;
    const int mbase = blockIdx.y * 128, nbase = blockIdx.x * 128;
    const int bz = blockIdx.z;
    const size_t zoff = (size_t)bz * Nq * CK;

    #pragma unroll
    for (int i = 0; i < 2; i++) {
        int idx = t + i * 256;
        int r = idx >> 2, seg = idx & 3;
        uint32_t so = r * 80 + seg * 16;
        cp16(base + GH_OFF + so, g_g  + zoff + (size_t)(mbase + r) * CK + seg * 8);
        cp16(base + GL_OFF + so, g_gl + zoff + (size_t)(mbase + r) * CK + seg * 8);
        cp16(base + FH_OFF + so, g_f  + zoff + (size_t)(nbase + r) * CK + seg * 8);
        cp16(base + FL_OFF + so, g_fl + zoff + (size_t)(nbase + r) * CK + seg * 8);
    }
    cp_commit();
    asm volatile("cp.async.wait_group 0;" ::: "memory");
    __syncthreads();

    const int arow   = (lane & 7) + ((lane >> 3) & 1) * 8;
    const int acol16 = (lane >> 4) * 16;
    const int brow   = (lane >> 4) * 8 + (lane & 7);
    const int bcol16 = ((lane >> 3) & 1) * 16;

    float acc[4][4][4] = {};
    #pragma unroll
    for (int ks = 0; ks < 2; ks++) {
        uint32_t ah[4][4], al[4][4];
        #pragma unroll
        for (int mt = 0; mt < 4; mt++) {
            uint32_t off = (wm * 64 + mt * 16 + arow) * 80 + ks * 32 + acol16;
            ldsm4(ah[mt], base + GH_OFF + off);
            ldsm4(al[mt], base + GL_OFF + off);
        }
        #pragma unroll
        for (int j = 0; j < 2; j++) {
            uint32_t bh[4], bl[4];
            uint32_t off = (wn * 32 + j * 16 + brow) * 80 + ks * 32 + bcol16;
            ldsm4(bh, base + FH_OFF + off);
            ldsm4(bl, base + FL_OFF + off);
            #pragma unroll
            for (int sub = 0; sub < 2; sub++) {
                #pragma unroll
                for (int mt = 0; mt < 4; mt++) {
                    mma_f16(acc[mt][2 * j + sub], ah[mt], bh + sub * 2);
                    mma_f16(acc[mt][2 * j + sub], ah[mt], bl + sub * 2);
                    mma_f16(acc[mt][2 * j + sub], al[mt], bh + sub * 2);
                }
            }
        }
    }

    float* sout = g_s + (size_t)bz * Nq * Nq;
    #pragma unroll
    for (int mt = 0; mt < 4; mt++) {
        int r0 = mbase + wm * 64 + mt * 16 + (lane >> 2);
        float mx0 = -3.4e38f, mx1 = -3.4e38f;
        #pragma unroll
        for (int nt = 0; nt < 4; nt++) {
            int col = nbase + wn * 32 + nt * 8 + 2 * (lane & 3);
            float2 o0; o0.x = acc[mt][nt][0]; o0.y = acc[mt][nt][1];
            *(float2*)(sout + (size_t)r0 * Nq + col) = o0;
            float2 o1; o1.x = acc[mt][nt][2]; o1.y = acc[mt][nt][3];
            *(float2*)(sout + (size_t)(r0 + 8) * Nq + col) = o1;
            mx0 = fmaxf(mx0, fmaxf(o0.x, o0.y));
            mx1 = fmaxf(mx1, fmaxf(o1.x, o1.y));
        }
        mx0 = fmaxf(mx0, __shfl_xor_sync(0xffffffffu, mx0, 1));
        mx0 = fmaxf(mx0, __shfl_xor_sync(0xffffffffu, mx0, 2));
        mx1 = fmaxf(mx1, __shfl_xor_sync(0xffffffffu, mx1, 1));
        mx1 = fmaxf(mx1, __shfl_xor_sync(0xffffffffu, mx1, 2));
        if ((lane & 3) == 0) {
            atomicMax(&g_rowmaxE[bz * Nq + r0],     fenc(mx0));
            atomicMax(&g_rowmaxE[bz * Nq + r0 + 8], fenc(mx1));
        }
    }
}

// ===========================================================================
// Kernel 3: fused softmax + PV (fp16 mma) + residual.  BK=64 chunks.
//   512 threads, 16 warps (2m x 8n), warp tile 64x32.
//   Producer (exp/LDG) interleaved BETWEEN the two mma halves so MUFU/LSU
//   overlap the tensor pipe instead of preceding it on the critical path.
// ===========================================================================
constexpr int PV_PITCH = 144;
constexpr int PV_A_ST  = 128 * PV_PITCH;            // 18432
constexpr int PV_B_ST  = 256 * PV_PITCH;            // 36864
constexpr int PV_A_OFF = 0;                         // 3 stages: 55296
constexpr int PV_B_OFF = 3 * PV_A_ST;               // 3 stages: 110592
constexpr int PV_Z_OFF = PV_B_OFF + 3 * PV_B_ST;    // 165888
constexpr int PV_SMEM  = PV_Z_OFF + 512;            // 166400
constexpr int NCH = Nq / 64;                        // 64

__global__ __launch_bounds__(512, 1)
void pv_kernel(const float* __restrict__ gamma_p,
               const float* __restrict__ x, float* __restrict__ y) {
    extern __shared__ char dsm[];
    const uint32_t base = smem_u32(dsm);
    float* zsm = (float*)(dsm + PV_Z_OFF);

    const int t = threadIdx.x;
    const int lane = t & 31, wid = t >> 5;
    const int wm = wid >> 3, wn = wid & 7;         // 2(M) x 8(N)
    const int qbase = blockIdx.x * 128;
    const int b = blockIdx.y;
    const float*  Pm  = g_s  + (size_t)b * Nq * Nq;
    const __half* hTb = g_hT + (size_t)b * C * Nq;

    if (t < 128) zsm[t] = 0.f;

    const int tr = t >> 2;           // 0..127: one q-row per thread
    const int cb = (t & 3) * 16;     // 16 contiguous cols per thread

    const int arow   = (lane & 7) + ((lane >> 3) & 1) * 8;
    const int acol16 = (lane >> 4) * 16;
    const int brow   = (lane >> 4) * 8 + (lane & 7);
    const int bcol16 = ((lane >> 3) & 1) * 16;

    const float rm = fdec(g_rowmaxE[b * Nq + qbase + tr]);

    float4 va[4];
    float zp = 0.f;

    auto ldgA = [&](int chunk) {
        const float* bp = Pm + (size_t)(qbase + tr) * Nq + chunk * 64 + cb;
        #pragma unroll
        for (int i = 0; i < 4; i++)
            va[i] = *(const float4*)(bp + i * 4);
    };
    auto expSts = [&](int chunk) {
        char* Ad = dsm + PV_A_OFF + (chunk % 3) * PV_A_ST;
        #pragma unroll
        for (int i = 0; i < 4; i++) {
            float p0 = __expf(va[i].x - rm);
            float p1 = __expf(va[i].y - rm);
            float p2 = __expf(va[i].z - rm);
            float p3 = __expf(va[i].w - rm);
            zp += (p0 + p1) + (p2 + p3);
            uint2 u;
            u.x = pack2(__float2half_rn(p0), __float2half_rn(p1));
            u.y = pack2(__float2half_rn(p2), __float2half_rn(p3));
            *(uint2*)(Ad + tr * PV_PITCH + (cb + i * 4) * 2) = u;
        }
    };
    auto cpB = [&](int chunk) {
        uint32_t Bd = base + PV_B_OFF + (chunk % 3) * PV_B_ST;
        #pragma unroll
        for (int i = 0; i < 4; i++) {
            int idx = t + i * 512;
            int r = idx >> 3, seg = idx & 7;
            cp16(Bd + r * PV_PITCH + seg * 16, hTb + (size_t)r * Nq + chunk * 64 + seg * 8);
        }
        cp_commit();
    };

    // prologue: B0,B1 in flight; A0 in smem; va = raw chunk 1
    cpB(0); cpB(1);
    ldgA(0);
    expSts(0);
    ldgA(1);
    asm volatile("cp.async.wait_group 1;" ::: "memory");   // B0 ready
    __syncthreads();                                        // A0 visible

    float acc[4][4][4] = {};   // warp tile 64(M) x 32(N)

    for (int c = 0; c < NCH; c++) {
        if (c + 2 < NCH) cpB(c + 2);   // stage freed by last barrier

        const uint32_t AsbU = base + PV_A_OFF + (c % 3) * PV_A_ST;
        const uint32_t BsbU = base + PV_B_OFF + (c % 3) * PV_B_ST;

        // ---- mma ks = 0,1 ----
        #pragma unroll
        for (int ks = 0; ks < 2; ks++) {
            uint32_t af[4][4];
            #pragma unroll
            for (int mt = 0; mt < 4; mt++)
                ldsm4(af[mt], AsbU + (wm * 64 + mt * 16 + arow) * PV_PITCH + ks * 32 + acol16);
            #pragma unroll
            for (int j = 0; j < 2; j++) {
                uint32_t bf[4];
                ldsm4(bf, BsbU + (wn * 32 + j * 16 + brow) * PV_PITCH + ks * 32 + bcol16);
                #pragma unroll
                for (int mt = 0; mt < 4; mt++) {
                    mma_f16(acc[mt][2 * j + 0], af[mt], bf + 0);
                    mma_f16(acc[mt][2 * j + 1], af[mt], bf + 2);
                }
            }
        }

        // ---- producer work overlaps tensor drain of ks=0,1 ----
        if (c + 1 < NCH) expSts(c + 1);     // consumes va (chunk c+1)
        if (c + 2 < NCH) ldgA(c + 2);       // refills va

        // ---- mma ks = 2,3 ----
        #pragma unroll
        for (int ks = 2; ks < 4; ks++) {
            uint32_t af[4][4];
            #pragma unroll
            for (int mt = 0; mt < 4; mt++)
                ldsm4(af[mt], AsbU + (wm * 64 + mt * 16 + arow) * PV_PITCH + ks * 32 + acol16);
            #pragma unroll
            for (int j = 0; j < 2; j++) {
                uint32_t bf[4];
                ldsm4(bf, BsbU + (wn * 32 + j * 16 + brow) * PV_PITCH + ks * 32 + bcol16);
                #pragma unroll
                for (int mt = 0; mt < 4; mt++) {
                    mma_f16(acc[mt][2 * j + 0], af[mt], bf + 0);
                    mma_f16(acc[mt][2 * j + 1], af[mt], bf + 2);
                }
            }
        }

        if (c + 2 < NCH)      asm volatile("cp.async.wait_group 1;" ::: "memory");
        else if (c + 1 < NCH) asm volatile("cp.async.wait_group 0;" ::: "memory");
        __syncthreads();
    }

    atomicAdd(&zsm[tr], zp);
    __syncthreads();

    const float gam = __ldg(gamma_p);
    #pragma unroll
    for (int mt = 0; mt < 4; mt++) {
        int row0 = wm * 64 + mt * 16 + (lane >> 2);
        float sc0 = gam / zsm[row0];
        float sc1 = gam / zsm[row0 + 8];
        #pragma unroll
        for (int nt = 0; nt < 4; nt++) {
            int col = wn * 32 + nt * 8 + 2 * (lane & 3);
            size_t bo = ((size_t)b * Nq + qbase + row0) * C + col;
            float2 x0 = *(const float2*)(x + bo);
            float2 o0;
            o0.x = sc0 * acc[mt][nt][0] + x0.x;
            o0.y = sc0 * acc[mt][nt][1] + x0.y;
            *(float2*)(y + bo) = o0;
            size_t bo2 = bo + 8 * (size_t)C;
            float2 x1 = *(const float2*)(x + bo2);
            float2 o1;
            o1.x = sc1 * acc[mt][nt][2] + x1.x;
            o1.y = sc1 * acc[mt][nt][3] + x1.y;
            *(float2*)(y + bo2) = o1;
        }
    }
}

// ===========================================================================
extern "C" void kernel_launch(void* const* d_in, const int* in_sizes, int n_in,
                              void* d_out, int out_size) {
    (void)in_sizes; (void)n_in; (void)out_size;
    const float* x     = (const float*)d_in[0];
    const float* Wf    = (const float*)d_in[1];
    const float* bf    = (const float*)d_in[2];
    const float* Wg    = (const float*)d_in[3];
    const float* bg    = (const float*)d_in[4];
    const float* Wh    = (const float*)d_in[5];
    const float* bh    = (const float*)d_in[6];
    const float* gamma = (const float*)d_in[7];
    float* y = (float*)d_out;

    cudaFuncSetAttribute(proj_kernel, cudaFuncAttributeMaxDynamicSharedMemorySize, PJ_SMEM);
    cudaFuncSetAttribute(score_kernel, cudaFuncAttributeMaxDynamicSharedMemorySize, SC_SMEM);
    cudaFuncSetAttribute(pv_kernel, cudaFuncAttributeMaxDynamicSharedMemorySize, PV_SMEM);

    wtrans_kernel<<<320, 256>>>(Wf, Wg, Wh);
    proj_kernel<<<(Bb * Nq) / 64, 256, PJ_SMEM>>>(x, bf, bg, bh);
    score_kernel<<<dim3(Nq / 128, Nq / 128, Bb), 256, SC_SMEM>>>();
    pv_kernel<<<dim3(Nq / 128, Bb), 512, PV_SMEM>>>(gamma, x, y);
}